// round 12
// baseline (speedup 1.0000x reference)
#include <cuda_runtime.h>
#include <cuda_fp16.h>
#include <math.h>
#include <stdint.h>

// ---------------- problem constants ----------------
#define NN 20000
#define EE 160000
#define CC 768
#define HH 8
#define DD 96
#define GG 256
#define NCLS 32
#define C3 (3*CC)
#define ETOT (EE+NN)

// ---------------- device scratch (static, no allocs) ----------------
__device__ float g_h[(size_t)NN*CC];
__device__ float g_xl[(size_t)NN*CC];
__device__ float g_xr[(size_t)NN*CC];
__device__ float g_pooled[(size_t)GG*C3];

__device__ __half g_ah[(size_t)NN*CC];   // fp16 of x (input gemm A)
__device__ __half g_bh[(size_t)NN*CC];   // fp16 of h (layer gemm A)
__device__ __half g_wT[(size_t)7*CC*CC]; // fp16 transposed weights [gemm][N][K]

__device__ int g_src[EE];
__device__ int g_dst[EE];
__device__ int g_batchi[NN];
__device__ int g_cnt[NN];
__device__ int g_cur[NN];
__device__ int g_off[NN+1];
__device__ int g_csrsrc[ETOT];
#define SCAN_NCH 20
__device__ int g_chsum[SCAN_NCH];
__device__ int g_choff[SCAN_NCH];
__device__ int g_gstart[GG+1];
__device__ int g_is64;

// ---------------- PTX helpers (plain sm_80-era PTX only) ----------------
__device__ __forceinline__ uint32_t smem_u32(const void* p) {
    uint32_t a;
    asm("{ .reg .u64 t; cvta.to.shared.u64 t, %1; cvt.u32.u64 %0, t; }" : "=r"(a) : "l"(p));
    return a;
}
__device__ __forceinline__ void cpa16(uint32_t dst, const void* src) {
    asm volatile("cp.async.cg.shared.global [%0], [%1], 16;" :: "r"(dst), "l"(src));
}
#define CP_COMMIT() asm volatile("cp.async.commit_group;" ::: "memory")
#define CP_WAIT(n)  asm volatile("cp.async.wait_group %0;" ::"n"(n):"memory")

__device__ __forceinline__ void ldm_x4(uint32_t& r0, uint32_t& r1, uint32_t& r2, uint32_t& r3, uint32_t addr) {
    asm volatile("ldmatrix.sync.aligned.m8n8.x4.shared.b16 {%0,%1,%2,%3}, [%4];"
                 : "=r"(r0), "=r"(r1), "=r"(r2), "=r"(r3) : "r"(addr));
}
__device__ __forceinline__ void mma16816(float& c0, float& c1, float& c2, float& c3,
                                         uint32_t a0, uint32_t a1, uint32_t a2, uint32_t a3,
                                         uint32_t b0, uint32_t b1) {
    asm volatile("mma.sync.aligned.m16n8k16.row.col.f32.f16.f16.f32 "
                 "{%0,%1,%2,%3},{%4,%5,%6,%7},{%8,%9},{%0,%1,%2,%3};"
                 : "+f"(c0), "+f"(c1), "+f"(c2), "+f"(c3)
                 : "r"(a0), "r"(a1), "r"(a2), "r"(a3), "r"(b0), "r"(b1));
}

// ---------------- weight transpose to fp16: g_wT[g][n][k] = fp16(W_g[k][n]) ----------------
__global__ __launch_bounds__(1024) void k_transpose(
    const float* __restrict__ w_in, const float* __restrict__ Wl, const float* __restrict__ Wr)
{
    __shared__ float t[32][33];
    int g = blockIdx.z;
    const float* src;
    if (g == 0) src = w_in;
    else {
        int l = (g - 1) >> 1;
        src = (((g - 1) & 1) == 0 ? Wl : Wr) + (size_t)l * CC * CC;
    }
    int x = blockIdx.x * 32 + threadIdx.x;   // n
    int y = blockIdx.y * 32 + threadIdx.y;   // k
    t[threadIdx.y][threadIdx.x] = src[(size_t)y * CC + x];
    __syncthreads();
    int on = blockIdx.x * 32 + threadIdx.y;
    int ok = blockIdx.y * 32 + threadIdx.x;
    g_wT[(size_t)g * CC * CC + (size_t)on * CC + ok] = __float2half(t[threadIdx.x][threadIdx.y]);
}

// ---------------- fp16 convert of x ----------------
__global__ __launch_bounds__(256) void k_split_x(const float* __restrict__ in) {
    int i = blockIdx.x * blockDim.x + threadIdx.x;
    if (i >= NN * CC / 4) return;
    float4 v = *(const float4*)(in + (size_t)i * 4);
    __half h0 = __float2half(v.x), h1 = __float2half(v.y);
    __half h2 = __float2half(v.z), h3 = __float2half(v.w);
    ushort4 hv = make_ushort4(*(unsigned short*)&h0, *(unsigned short*)&h1,
                              *(unsigned short*)&h2, *(unsigned short*)&h3);
    *(ushort4*)(g_ah + (size_t)i * 4) = hv;
}

// ---------------- index dtype detection + CSR build ----------------
__global__ void k_detect(const void* eraw) {
    const unsigned int* p = (const unsigned int*)eraw;
    unsigned int acc = 0;
#pragma unroll
    for (int j = 0; j < 8; ++j) acc |= p[2*j + 1];
    g_is64 = (acc == 0u) ? 1 : 0;
}

__global__ void k_prep() {
    int i = blockIdx.x * blockDim.x + threadIdx.x;
    if (i < NN) { g_cnt[i] = 1; g_cur[i] = 1; }
}

__global__ void k_convert_count(const void* eraw, const void* braw) {
    int i = blockIdx.x * blockDim.x + threadIdx.x;
    int is64 = g_is64;
    if (i < EE) {
        int s, d;
        if (is64) {
            const long long* p = (const long long*)eraw;
            s = (int)p[i]; d = (int)p[EE + i];
        } else {
            const int* p = (const int*)eraw;
            s = p[i]; d = p[EE + i];
        }
        g_src[i] = s; g_dst[i] = d;
        atomicAdd(&g_cnt[d], 1);
    }
    if (i < NN) {
        if (is64) {
            const long long* p = (const long long*)braw;
            g_batchi[i] = (int)p[i];
        } else {
            const int* p = (const int*)braw;
            g_batchi[i] = p[i];
        }
    }
}

__global__ __launch_bounds__(1024) void k_chsum() {
    __shared__ int sh[1024];
    int t = threadIdx.x;
    int i = blockIdx.x * 1024 + t;
    sh[t] = (i < NN) ? g_cnt[i] : 0;
    __syncthreads();
    for (int o = 512; o > 0; o >>= 1) {
        if (t < o) sh[t] += sh[t + o];
        __syncthreads();
    }
    if (t == 0) g_chsum[blockIdx.x] = sh[0];
}

__global__ void k_choff() {
    if (threadIdx.x == 0 && blockIdx.x == 0) {
        int run = 0;
        for (int i = 0; i < SCAN_NCH; ++i) { g_choff[i] = run; run += g_chsum[i]; }
        g_off[NN] = run;
    }
}

__global__ __launch_bounds__(1024) void k_offsets() {
    __shared__ int sh[1024];
    int t = threadIdx.x;
    int i = blockIdx.x * 1024 + t;
    int v = (i < NN) ? g_cnt[i] : 0;
    sh[t] = v;
    __syncthreads();
#pragma unroll
    for (int o = 1; o < 1024; o <<= 1) {
        int add = (t >= o) ? sh[t - o] : 0;
        __syncthreads();
        sh[t] += add;
        __syncthreads();
    }
    if (i < NN) g_off[i] = sh[t] - v + g_choff[blockIdx.x];
}

__global__ void k_csrfill() {
    int i = blockIdx.x * blockDim.x + threadIdx.x;
    if (i < NN) g_csrsrc[g_off[i]] = i;
    if (i < EE) {
        int d = g_dst[i];
        int slot = g_off[d] + atomicAdd(&g_cur[d], 1);
        g_csrsrc[slot] = g_src[i];
    }
}

__global__ void k_gstart() {
    int i = blockIdx.x * blockDim.x + threadIdx.x;
    if (i == 0) {
        int b = g_batchi[0];
        for (int g = 0; g <= b; ++g) g_gstart[g] = 0;
    } else if (i < NN) {
        int b0 = g_batchi[i - 1], b1 = g_batchi[i];
        for (int g = b0 + 1; g <= b1; ++g) g_gstart[g] = i;
    } else if (i == NN) {
        int b = g_batchi[NN - 1];
        for (int g = b + 1; g <= GG; ++g) g_gstart[g] = NN;
    }
}

// ---------------- fp16 single-pass tensor-core GEMM (128x128 tile, 2 CTAs/SM) ----------------
#define ROWB 80                 // 64B data + 16B pad
#define TILE_A 10240            // 128 rows * 80B
#define STAGE_B 20480           // A + B (128 rows each)
#define STG 5
#define GEMM_SMEM (STG*STAGE_B) // 102.4 KB -> 2 CTAs/SM
#define NSTAGE 24               // 768 / 32

__device__ __forceinline__ void gemm_load_stage(
    const __half* __restrict__ Ah, const __half* __restrict__ Bh,
    int m0, int n0, int M, int kblk, uint32_t sb, int tid)
{
#pragma unroll
    for (int i = 0; i < 4; ++i) {
        int q = tid + i * 256;        // 0..1023
        int row = q >> 2, ch = q & 3;
        if (row < 128) {
            int ar = m0 + row; ar = (ar < M) ? ar : (M - 1);
            cpa16(sb + (uint32_t)(row * ROWB + ch * 16),
                  Ah + (size_t)ar * CC + kblk * 32 + ch * 8);
        } else {
            int br = row - 128;
            cpa16(sb + TILE_A + (uint32_t)(br * ROWB + ch * 16),
                  Bh + (size_t)(n0 + br) * CC + kblk * 32 + ch * 8);
        }
    }
    CP_COMMIT();
}

__device__ __forceinline__ void load_a_frags(uint32_t stg, uint32_t aoff, uint32_t* fa) {
    ldm_x4(fa[0], fa[1], fa[2], fa[3], stg + aoff);
    ldm_x4(fa[4], fa[5], fa[6], fa[7], stg + aoff + 16 * ROWB);
}
__device__ __forceinline__ void load_b_frags(uint32_t stg, uint32_t boff, uint32_t* fb) {
#pragma unroll
    for (int nc = 0; nc < 4; ++nc)
        ldm_x4(fb[nc*4+0], fb[nc*4+1], fb[nc*4+2], fb[nc*4+3],
               stg + TILE_A + boff + nc * 16 * ROWB);
}

__device__ __forceinline__ void mma_block(const uint32_t* fa, const uint32_t* fb,
                                          float acc[2][8][4])
{
#pragma unroll
    for (int nc = 0; nc < 4; ++nc) {
#pragma unroll
        for (int sub = 0; sub < 2; ++sub) {
            int nt = nc * 2 + sub;
            uint32_t b0 = fb[nc * 4 + sub * 2], b1 = fb[nc * 4 + sub * 2 + 1];
            mma16816(acc[0][nt][0], acc[0][nt][1], acc[0][nt][2], acc[0][nt][3],
                     fa[0], fa[1], fa[2], fa[3], b0, b1);
            mma16816(acc[1][nt][0], acc[1][nt][1], acc[1][nt][2], acc[1][nt][3],
                     fa[4], fa[5], fa[6], fa[7], b0, b1);
        }
    }
}

__global__ __launch_bounds__(256, 2) void k_gemm_mma(
    const __half* __restrict__ Ah, const __half* __restrict__ Bh,
    const float* __restrict__ bias0, const float* __restrict__ bias1,
    float* __restrict__ C0, float* __restrict__ C1, int M, int do_split)
{
    extern __shared__ char smraw[];
    uint32_t sb = smem_u32(smraw);
    const int tid = threadIdx.x;
    const int wid = tid >> 5, lane = tid & 31;
    const int wm = wid >> 1, wn = wid & 1;          // 4 x 2 warps -> 128 x 128
    const int n0 = blockIdx.x * 128, m0 = blockIdx.y * 128;

    const int arow = lane & 15;
    const uint32_t aoff = (uint32_t)((wm * 32 + arow) * ROWB + (lane >> 4) * 16);
    const int brow = (lane & 7) | ((lane >> 4) << 3);
    const uint32_t boff = (uint32_t)((wn * 64 + brow) * ROWB + ((lane >> 3) & 1) * 16);

    float acc[2][8][4];
#pragma unroll
    for (int a = 0; a < 2; ++a)
#pragma unroll
        for (int b = 0; b < 8; ++b)
#pragma unroll
            for (int c = 0; c < 4; ++c) acc[a][b][c] = 0.f;

    uint32_t fa0[8], fa1[8];   // A double-buffered
    uint32_t fb[16];           // B single-buffered

#pragma unroll
    for (int s = 0; s < 4; ++s)
        gemm_load_stage(Ah, Bh, m0, n0, M, s, sb + s * STAGE_B, tid);
    CP_WAIT(3);
    __syncthreads();
    load_a_frags(sb, aoff, fa0);

    for (int stage = 0; stage < NSTAGE; ++stage) {
        uint32_t slot = sb + (stage % STG) * STAGE_B;

        if (stage + 4 < NSTAGE)
            gemm_load_stage(Ah, Bh, m0, n0, M, stage + 4,
                            sb + ((stage + 4) % STG) * STAGE_B, tid);
        else
            CP_COMMIT();

        load_a_frags(slot + 32, aoff, fa1);
        load_b_frags(slot, boff, fb);

        mma_block(fa0, fb, acc);

        load_b_frags(slot + 32, boff, fb);

        if (stage + 1 < NSTAGE) {
            CP_WAIT(3);
            __syncthreads();
            load_a_frags(sb + ((stage + 1) % STG) * STAGE_B, aoff, fa0);
        }

        mma_block(fa1, fb, acc);
    }

    // epilogue: route columns to C0 or C1
    float* Cout = C0;
    const float* bp = bias0;
    int coloff = n0;
    if (n0 >= CC) { Cout = C1; bp = bias1; coloff = n0 - CC; }

    const int g = lane >> 2, tg = lane & 3;
#pragma unroll
    for (int mt = 0; mt < 2; ++mt) {
        int r0 = m0 + wm * 32 + mt * 16 + g;
#pragma unroll
        for (int nt = 0; nt < 8; ++nt) {
            int col = coloff + wn * 64 + nt * 8 + 2 * tg;
            float bx = bp[col], by = bp[col + 1];
#pragma unroll
            for (int half = 0; half < 2; ++half) {
                int row = r0 + half * 8;
                if (row < M) {
                    float vx = acc[mt][nt][half * 2]     + bx;
                    float vy = acc[mt][nt][half * 2 + 1] + by;
                    *(float2*)(Cout + (size_t)row * CC + col) = make_float2(vx, vy);
                    if (do_split) {
                        __half hx = __float2half(vx);
                        __half hy = __float2half(vy);
                        size_t o = (size_t)row * CC + col;
                        *(ushort2*)(g_bh + o) = make_ushort2(*(unsigned short*)&hx, *(unsigned short*)&hy);
                    }
                }
            }
        }
    }
}

// ---------------- fused GATv2 attention + aggregate + residual + LN + GELU + convert ----------------
// Edge loop software-pipelined with 1-edge lookahead (hides L2 gather latency).
__global__ __launch_bounds__(256) void k_aggregate(
    const float* __restrict__ att, const float* __restrict__ gbias,
    const float* __restrict__ lnw, const float* __restrict__ lnb, int layer)
{
    const int v = blockIdx.x;
    const int tid = threadIdx.x;
    const int w = tid >> 5, lane = tid & 31;
    const int c0 = w * DD + lane;

    const float* attL = att + (size_t)layer * CC;
    float a0 = attL[c0], a1 = attL[c0 + 32], a2 = attL[c0 + 64];
    const float* xrv = g_xr + (size_t)v * CC;
    float r0 = xrv[c0], r1 = xrv[c0 + 32], r2 = xrv[c0 + 64];

    int e0 = g_off[v], e1 = g_off[v + 1];
    float m = -INFINITY, s = 0.f, acc0 = 0.f, acc1 = 0.f, acc2 = 0.f;

    // preload edge e0 (self loop guarantees e1 > e0)
    int src = g_csrsrc[e0];
    const float* xv = g_xl + (size_t)src * CC + c0;
    float v0 = xv[0], v1 = xv[32], v2 = xv[64];

    for (int e = e0; e < e1; ++e) {
        // prefetch next edge's values while computing this edge
        float n0 = 0.f, n1 = 0.f, n2 = 0.f;
        if (e + 1 < e1) {
            int ns = g_csrsrc[e + 1];
            const float* nx = g_xl + (size_t)ns * CC + c0;
            n0 = nx[0]; n1 = nx[32]; n2 = nx[64];
        }

        float t0 = v0 + r0; t0 = (t0 > 0.f) ? t0 : 0.2f * t0;
        float t1 = v1 + r1; t1 = (t1 > 0.f) ? t1 : 0.2f * t1;
        float t2 = v2 + r2; t2 = (t2 > 0.f) ? t2 : 0.2f * t2;
        float p = t0 * a0 + t1 * a1 + t2 * a2;
#pragma unroll
        for (int o = 16; o > 0; o >>= 1) p += __shfl_xor_sync(0xffffffffu, p, o);
        float mn = fmaxf(m, p);
        float corr = __expf(m - mn);
        float wt = __expf(p - mn);
        s = s * corr + wt;
        acc0 = acc0 * corr + wt * v0;
        acc1 = acc1 * corr + wt * v1;
        acc2 = acc2 * corr + wt * v2;
        m = mn;

        v0 = n0; v1 = n1; v2 = n2;
    }

    float inv = 1.f / s;
    const float* gb = gbias + (size_t)layer * CC;
    const float* hv = g_h + (size_t)v * CC;
    float t0 = acc0 * inv + gb[c0]      + hv[c0];
    float t1 = acc1 * inv + gb[c0 + 32] + hv[c0 + 32];
    float t2 = acc2 * inv + gb[c0 + 64] + hv[c0 + 64];

    float ls = t0 + t1 + t2;
    float lq = t0 * t0 + t1 * t1 + t2 * t2;
#pragma unroll
    for (int o = 16; o > 0; o >>= 1) {
        ls += __shfl_xor_sync(0xffffffffu, ls, o);
        lq += __shfl_xor_sync(0xffffffffu, lq, o);
    }
    __shared__ float shs[8], shq[8];
    if (lane == 0) { shs[w] = ls; shq[w] = lq; }
    __syncthreads();
    float S = 0.f, Q = 0.f;
#pragma unroll
    for (int i = 0; i < 8; ++i) { S += shs[i]; Q += shq[i]; }
    float mu = S * (1.f / 768.f);
    float var = Q * (1.f / 768.f) - mu * mu;
    float rs = rsqrtf(var + 1e-5f);

    const float* lw = lnw + (size_t)layer * CC;
    const float* lb = lnb + (size_t)layer * CC;
    float y0 = (t0 - mu) * rs * lw[c0]      + lb[c0];
    float y1 = (t1 - mu) * rs * lw[c0 + 32] + lb[c0 + 32];
    float y2 = (t2 - mu) * rs * lw[c0 + 64] + lb[c0 + 64];

    float gA = 0.5f * y0 * (1.f + erff(y0 * 0.70710678118654752f));
    float gB = 0.5f * y1 * (1.f + erff(y1 * 0.70710678118654752f));
    float gC = 0.5f * y2 * (1.f + erff(y2 * 0.70710678118654752f));

    float* hw = g_h + (size_t)v * CC;
    hw[c0] = gA; hw[c0 + 32] = gB; hw[c0 + 64] = gC;

    size_t ob = (size_t)v * CC;
    g_bh[ob + c0]      = __float2half(gA);
    g_bh[ob + c0 + 32] = __float2half(gB);
    g_bh[ob + c0 + 64] = __float2half(gC);
}

// ---------------- per-layer mean pool over graphs (reads g_h, JK-cat slab) ----------------
__global__ __launch_bounds__(256) void k_pool_layer(int layer) {
    int g = blockIdx.x;
    int t = threadIdx.x;
    int s0 = g_gstart[g], s1 = g_gstart[g + 1];
    float a0 = 0.f, a1 = 0.f, a2 = 0.f;
    for (int i = s0; i < s1; ++i) {
        const float* r = g_h + (size_t)i * CC;
        a0 += r[t];
        a1 += r[t + 256];
        a2 += r[t + 512];
    }
    float inv = 1.f / fmaxf((float)(s1 - s0), 1.f);
    float* o = g_pooled + (size_t)g * C3 + (size_t)layer * CC;
    o[t]       = a0 * inv;
    o[t + 256] = a1 * inv;
    o[t + 512] = a2 * inv;
}

// ---------------- output LN + classifier ----------------
__global__ __launch_bounds__(256) void k_final(
    const float* __restrict__ lnw, const float* __restrict__ lnb,
    const float* __restrict__ wout, const float* __restrict__ bout,
    float* __restrict__ out)
{
    __shared__ float row[C3];
    __shared__ float red_s[8], red_q[8];
    __shared__ float sh_mu, sh_rs;
    int g = blockIdx.x, t = threadIdx.x;
    int lane = t & 31, w = t >> 5;

    float s = 0.f, q = 0.f;
    for (int c = t; c < C3; c += 256) {
        float v = g_pooled[(size_t)g * C3 + c];
        row[c] = v;
        s += v;
        q += v * v;
    }
#pragma unroll
    for (int o = 16; o > 0; o >>= 1) {
        s += __shfl_xor_sync(0xffffffffu, s, o);
        q += __shfl_xor_sync(0xffffffffu, q, o);
    }
    if (lane == 0) { red_s[w] = s; red_q[w] = q; }
    __syncthreads();
    if (t == 0) {
        float S = 0.f, Q = 0.f;
#pragma unroll
        for (int i = 0; i < 8; ++i) { S += red_s[i]; Q += red_q[i]; }
        float mu = S * (1.f / (float)C3);
        float var = Q * (1.f / (float)C3) - mu * mu;
        sh_mu = mu;
        sh_rs = rsqrtf(var + 1e-5f);
    }
    __syncthreads();
    float mu = sh_mu, rs = sh_rs;
    for (int c = t; c < C3; c += 256)
        row[c] = (row[c] - mu) * rs * lnw[c] + lnb[c];
    __syncthreads();

    for (int cls = w; cls < NCLS; cls += 8) {
        float p = 0.f;
        for (int i = lane; i < C3; i += 32)
            p += row[i] * wout[(size_t)i * NCLS + cls];
#pragma unroll
        for (int o = 16; o > 0; o >>= 1) p += __shfl_xor_sync(0xffffffffu, p, o);
        if (lane == 0) out[(size_t)g * NCLS + cls] = p + bout[cls];
    }
}

// ---------------- launch ----------------
extern "C" void kernel_launch(void* const* d_in, const int* in_sizes, int n_in,
                              void* d_out, int out_size)
{
    const float* x        = (const float*)d_in[0];
    const void*  eraw     = d_in[1];
    const void*  braw     = d_in[2];
    const float* w_in     = (const float*)d_in[3];
    const float* b_in     = (const float*)d_in[4];
    const float* Wl       = (const float*)d_in[5];
    const float* bl       = (const float*)d_in[6];
    const float* Wr       = (const float*)d_in[7];
    const float* br       = (const float*)d_in[8];
    const float* att      = (const float*)d_in[9];
    const float* gat_bias = (const float*)d_in[10];
    const float* ln_w     = (const float*)d_in[11];
    const float* ln_b     = (const float*)d_in[12];
    const float* out_ln_w = (const float*)d_in[13];
    const float* out_ln_b = (const float*)d_in[14];
    const float* w_out    = (const float*)d_in[15];
    const float* b_out    = (const float*)d_in[16];
    float* out = (float*)d_out;

    float *ph, *pxl, *pxr;
    __half *pah, *pbh, *pw;
    cudaGetSymbolAddress((void**)&ph,  g_h);
    cudaGetSymbolAddress((void**)&pxl, g_xl);
    cudaGetSymbolAddress((void**)&pxr, g_xr);
    cudaGetSymbolAddress((void**)&pah, g_ah);
    cudaGetSymbolAddress((void**)&pbh, g_bh);
    cudaGetSymbolAddress((void**)&pw,  g_wT);

    static int smem_set = 0;
    if (!smem_set) {
        cudaFuncSetAttribute(k_gemm_mma, cudaFuncAttributeMaxDynamicSharedMemorySize, GEMM_SMEM);
        smem_set = 1;
    }

    const int splitg = (NN * CC / 4 + 255) / 256;
    dim3 ggrid1(6, (NN + 127) / 128);    // input gemm: 768 cols / 128
    dim3 ggrid2(12, (NN + 127) / 128);   // fused Wl|Wr gemm: 1536 cols / 128

    // front-load so the profiler slot lands on the GEMM
    k_transpose<<<dim3(24, 24, 7), dim3(32, 32)>>>(w_in, Wl, Wr);
    k_split_x<<<splitg, 256>>>(x);
    k_detect<<<1, 1>>>(eraw);
    k_gemm_mma<<<ggrid1, 256, GEMM_SMEM>>>(pah, pw, b_in, b_in, ph, ph, NN, 1);

    // CSR build
    k_prep<<<(NN + 255) / 256, 256>>>();
    k_convert_count<<<(EE + 255) / 256, 256>>>(eraw, braw);
    k_chsum<<<SCAN_NCH, 1024>>>();
    k_choff<<<1, 32>>>();
    k_offsets<<<SCAN_NCH, 1024>>>();
    k_csrfill<<<(EE + 255) / 256, 256>>>();
    k_gstart<<<(NN + 256) / 256, 256>>>();

    for (int l = 0; l < 3; ++l) {
        const __half* BW = pw + (size_t)(1 + 2 * l) * CC * CC;   // Wl then Wr adjacent
        k_gemm_mma<<<ggrid2, 256, GEMM_SMEM>>>(pbh, BW,
                                               bl + (size_t)l * CC, br + (size_t)l * CC,
                                               pxl, pxr, NN, 0);
        k_aggregate<<<NN, 256>>>(att, gat_bias, ln_w, ln_b, l);
        k_pool_layer<<<GG, 256>>>(l);
    }

    k_final<<<GG, 256>>>(out_ln_w, out_ln_b, w_out, b_out, out);

    (void)in_sizes; (void)n_in; (void)out_size;
}

// round 13
// speedup vs baseline: 1.0124x; 1.0124x over previous
#include <cuda_runtime.h>
#include <cuda_fp16.h>
#include <math.h>
#include <stdint.h>

// ---------------- problem constants ----------------
#define NN 20000
#define EE 160000
#define CC 768
#define HH 8
#define DD 96
#define GG 256
#define NCLS 32
#define C3 (3*CC)
#define ETOT (EE+NN)

// ---------------- device scratch (static, no allocs) ----------------
__device__ float g_h[(size_t)NN*CC];
__device__ float g_pooled[(size_t)GG*C3];

__device__ __half g_xlh[(size_t)NN*CC];  // fp16 xl (layer gemm out)
__device__ __half g_xrh[(size_t)NN*CC];  // fp16 xr (layer gemm out)
__device__ __half g_ah[(size_t)NN*CC];   // fp16 of x (input gemm A)
__device__ __half g_bh[(size_t)NN*CC];   // fp16 of h (layer gemm A)
__device__ __half g_wT[(size_t)7*CC*CC]; // fp16 transposed weights [gemm][N][K]

__device__ int g_src[EE];
__device__ int g_dst[EE];
__device__ int g_batchi[NN];
__device__ int g_cnt[NN];
__device__ int g_cur[NN];
__device__ int g_off[NN+1];
__device__ int g_csrsrc[ETOT];
#define SCAN_NCH 20
__device__ int g_chsum[SCAN_NCH];
__device__ int g_choff[SCAN_NCH];
__device__ int g_gstart[GG+1];
__device__ int g_is64;

// ---------------- PTX helpers (plain sm_80-era PTX only) ----------------
__device__ __forceinline__ uint32_t smem_u32(const void* p) {
    uint32_t a;
    asm("{ .reg .u64 t; cvta.to.shared.u64 t, %1; cvt.u32.u64 %0, t; }" : "=r"(a) : "l"(p));
    return a;
}
__device__ __forceinline__ void cpa16(uint32_t dst, const void* src) {
    asm volatile("cp.async.cg.shared.global [%0], [%1], 16;" :: "r"(dst), "l"(src));
}
#define CP_COMMIT() asm volatile("cp.async.commit_group;" ::: "memory")
#define CP_WAIT(n)  asm volatile("cp.async.wait_group %0;" ::"n"(n):"memory")

__device__ __forceinline__ void ldm_x4(uint32_t& r0, uint32_t& r1, uint32_t& r2, uint32_t& r3, uint32_t addr) {
    asm volatile("ldmatrix.sync.aligned.m8n8.x4.shared.b16 {%0,%1,%2,%3}, [%4];"
                 : "=r"(r0), "=r"(r1), "=r"(r2), "=r"(r3) : "r"(addr));
}
__device__ __forceinline__ void mma16816(float& c0, float& c1, float& c2, float& c3,
                                         uint32_t a0, uint32_t a1, uint32_t a2, uint32_t a3,
                                         uint32_t b0, uint32_t b1) {
    asm volatile("mma.sync.aligned.m16n8k16.row.col.f32.f16.f16.f32 "
                 "{%0,%1,%2,%3},{%4,%5,%6,%7},{%8,%9},{%0,%1,%2,%3};"
                 : "+f"(c0), "+f"(c1), "+f"(c2), "+f"(c3)
                 : "r"(a0), "r"(a1), "r"(a2), "r"(a3), "r"(b0), "r"(b1));
}

// ---------------- weight transpose to fp16: g_wT[g][n][k] = fp16(W_g[k][n]) ----------------
__global__ __launch_bounds__(1024) void k_transpose(
    const float* __restrict__ w_in, const float* __restrict__ Wl, const float* __restrict__ Wr)
{
    __shared__ float t[32][33];
    int g = blockIdx.z;
    const float* src;
    if (g == 0) src = w_in;
    else {
        int l = (g - 1) >> 1;
        src = (((g - 1) & 1) == 0 ? Wl : Wr) + (size_t)l * CC * CC;
    }
    int x = blockIdx.x * 32 + threadIdx.x;   // n
    int y = blockIdx.y * 32 + threadIdx.y;   // k
    t[threadIdx.y][threadIdx.x] = src[(size_t)y * CC + x];
    __syncthreads();
    int on = blockIdx.x * 32 + threadIdx.y;
    int ok = blockIdx.y * 32 + threadIdx.x;
    g_wT[(size_t)g * CC * CC + (size_t)on * CC + ok] = __float2half(t[threadIdx.x][threadIdx.y]);
}

// ---------------- fp16 convert of x ----------------
__global__ __launch_bounds__(256) void k_split_x(const float* __restrict__ in) {
    int i = blockIdx.x * blockDim.x + threadIdx.x;
    if (i >= NN * CC / 4) return;
    float4 v = *(const float4*)(in + (size_t)i * 4);
    __half h0 = __float2half(v.x), h1 = __float2half(v.y);
    __half h2 = __float2half(v.z), h3 = __float2half(v.w);
    ushort4 hv = make_ushort4(*(unsigned short*)&h0, *(unsigned short*)&h1,
                              *(unsigned short*)&h2, *(unsigned short*)&h3);
    *(ushort4*)(g_ah + (size_t)i * 4) = hv;
}

// ---------------- index dtype detection + CSR build ----------------
__global__ void k_detect(const void* eraw) {
    const unsigned int* p = (const unsigned int*)eraw;
    unsigned int acc = 0;
#pragma unroll
    for (int j = 0; j < 8; ++j) acc |= p[2*j + 1];
    g_is64 = (acc == 0u) ? 1 : 0;
}

__global__ void k_prep() {
    int i = blockIdx.x * blockDim.x + threadIdx.x;
    if (i < NN) { g_cnt[i] = 1; g_cur[i] = 1; }
}

__global__ void k_convert_count(const void* eraw, const void* braw) {
    int i = blockIdx.x * blockDim.x + threadIdx.x;
    int is64 = g_is64;
    if (i < EE) {
        int s, d;
        if (is64) {
            const long long* p = (const long long*)eraw;
            s = (int)p[i]; d = (int)p[EE + i];
        } else {
            const int* p = (const int*)eraw;
            s = p[i]; d = p[EE + i];
        }
        g_src[i] = s; g_dst[i] = d;
        atomicAdd(&g_cnt[d], 1);
    }
    if (i < NN) {
        if (is64) {
            const long long* p = (const long long*)braw;
            g_batchi[i] = (int)p[i];
        } else {
            const int* p = (const int*)braw;
            g_batchi[i] = p[i];
        }
    }
}

__global__ __launch_bounds__(1024) void k_chsum() {
    __shared__ int sh[1024];
    int t = threadIdx.x;
    int i = blockIdx.x * 1024 + t;
    sh[t] = (i < NN) ? g_cnt[i] : 0;
    __syncthreads();
    for (int o = 512; o > 0; o >>= 1) {
        if (t < o) sh[t] += sh[t + o];
        __syncthreads();
    }
    if (t == 0) g_chsum[blockIdx.x] = sh[0];
}

__global__ void k_choff() {
    if (threadIdx.x == 0 && blockIdx.x == 0) {
        int run = 0;
        for (int i = 0; i < SCAN_NCH; ++i) { g_choff[i] = run; run += g_chsum[i]; }
        g_off[NN] = run;
    }
}

__global__ __launch_bounds__(1024) void k_offsets() {
    __shared__ int sh[1024];
    int t = threadIdx.x;
    int i = blockIdx.x * 1024 + t;
    int v = (i < NN) ? g_cnt[i] : 0;
    sh[t] = v;
    __syncthreads();
#pragma unroll
    for (int o = 1; o < 1024; o <<= 1) {
        int add = (t >= o) ? sh[t - o] : 0;
        __syncthreads();
        sh[t] += add;
        __syncthreads();
    }
    if (i < NN) g_off[i] = sh[t] - v + g_choff[blockIdx.x];
}

__global__ void k_csrfill() {
    int i = blockIdx.x * blockDim.x + threadIdx.x;
    if (i < NN) g_csrsrc[g_off[i]] = i;
    if (i < EE) {
        int d = g_dst[i];
        int slot = g_off[d] + atomicAdd(&g_cur[d], 1);
        g_csrsrc[slot] = g_src[i];
    }
}

__global__ void k_gstart() {
    int i = blockIdx.x * blockDim.x + threadIdx.x;
    if (i == 0) {
        int b = g_batchi[0];
        for (int g = 0; g <= b; ++g) g_gstart[g] = 0;
    } else if (i < NN) {
        int b0 = g_batchi[i - 1], b1 = g_batchi[i];
        for (int g = b0 + 1; g <= b1; ++g) g_gstart[g] = i;
    } else if (i == NN) {
        int b = g_batchi[NN - 1];
        for (int g = b + 1; g <= GG; ++g) g_gstart[g] = NN;
    }
}

// ---------------- fp16 single-pass tensor-core GEMM (128x128 tile, 2 CTAs/SM) ----------------
#define ROWB 80                 // 64B data + 16B pad
#define TILE_A 10240            // 128 rows * 80B
#define STAGE_B 20480           // A + B (128 rows each)
#define STG 5
#define GEMM_SMEM (STG*STAGE_B) // 102.4 KB -> 2 CTAs/SM
#define NSTAGE 24               // 768 / 32

__device__ __forceinline__ void gemm_load_stage(
    const __half* __restrict__ Ah, const __half* __restrict__ Bh,
    int m0, int n0, int M, int kblk, uint32_t sb, int tid)
{
#pragma unroll
    for (int i = 0; i < 4; ++i) {
        int q = tid + i * 256;        // 0..1023
        int row = q >> 2, ch = q & 3;
        if (row < 128) {
            int ar = m0 + row; ar = (ar < M) ? ar : (M - 1);
            cpa16(sb + (uint32_t)(row * ROWB + ch * 16),
                  Ah + (size_t)ar * CC + kblk * 32 + ch * 8);
        } else {
            int br = row - 128;
            cpa16(sb + TILE_A + (uint32_t)(br * ROWB + ch * 16),
                  Bh + (size_t)(n0 + br) * CC + kblk * 32 + ch * 8);
        }
    }
    CP_COMMIT();
}

__device__ __forceinline__ void load_a_frags(uint32_t stg, uint32_t aoff, uint32_t* fa) {
    ldm_x4(fa[0], fa[1], fa[2], fa[3], stg + aoff);
    ldm_x4(fa[4], fa[5], fa[6], fa[7], stg + aoff + 16 * ROWB);
}
__device__ __forceinline__ void load_b_frags(uint32_t stg, uint32_t boff, uint32_t* fb) {
#pragma unroll
    for (int nc = 0; nc < 4; ++nc)
        ldm_x4(fb[nc*4+0], fb[nc*4+1], fb[nc*4+2], fb[nc*4+3],
               stg + TILE_A + boff + nc * 16 * ROWB);
}

__device__ __forceinline__ void mma_block(const uint32_t* fa, const uint32_t* fb,
                                          float acc[2][8][4])
{
#pragma unroll
    for (int nc = 0; nc < 4; ++nc) {
#pragma unroll
        for (int sub = 0; sub < 2; ++sub) {
            int nt = nc * 2 + sub;
            uint32_t b0 = fb[nc * 4 + sub * 2], b1 = fb[nc * 4 + sub * 2 + 1];
            mma16816(acc[0][nt][0], acc[0][nt][1], acc[0][nt][2], acc[0][nt][3],
                     fa[0], fa[1], fa[2], fa[3], b0, b1);
            mma16816(acc[1][nt][0], acc[1][nt][1], acc[1][nt][2], acc[1][nt][3],
                     fa[4], fa[5], fa[6], fa[7], b0, b1);
        }
    }
}

// mode 1 (input gemm): write fp32 Cf + fp16 g_bh.  mode 2 (layer gemm): write fp16 H0/H1 only.
__global__ __launch_bounds__(256, 2) void k_gemm_mma(
    const __half* __restrict__ Ah, const __half* __restrict__ Bh,
    const float* __restrict__ bias0, const float* __restrict__ bias1,
    float* __restrict__ Cf, __half* __restrict__ H0, __half* __restrict__ H1,
    int M, int mode)
{
    extern __shared__ char smraw[];
    uint32_t sb = smem_u32(smraw);
    const int tid = threadIdx.x;
    const int wid = tid >> 5, lane = tid & 31;
    const int wm = wid >> 1, wn = wid & 1;          // 4 x 2 warps -> 128 x 128
    const int n0 = blockIdx.x * 128, m0 = blockIdx.y * 128;

    const int arow = lane & 15;
    const uint32_t aoff = (uint32_t)((wm * 32 + arow) * ROWB + (lane >> 4) * 16);
    const int brow = (lane & 7) | ((lane >> 4) << 3);
    const uint32_t boff = (uint32_t)((wn * 64 + brow) * ROWB + ((lane >> 3) & 1) * 16);

    float acc[2][8][4];
#pragma unroll
    for (int a = 0; a < 2; ++a)
#pragma unroll
        for (int b = 0; b < 8; ++b)
#pragma unroll
            for (int c = 0; c < 4; ++c) acc[a][b][c] = 0.f;

    uint32_t fa0[8], fa1[8];   // A double-buffered
    uint32_t fb[16];           // B single-buffered

#pragma unroll
    for (int s = 0; s < 4; ++s)
        gemm_load_stage(Ah, Bh, m0, n0, M, s, sb + s * STAGE_B, tid);
    CP_WAIT(3);
    __syncthreads();
    load_a_frags(sb, aoff, fa0);

    for (int stage = 0; stage < NSTAGE; ++stage) {
        uint32_t slot = sb + (stage % STG) * STAGE_B;

        if (stage + 4 < NSTAGE)
            gemm_load_stage(Ah, Bh, m0, n0, M, stage + 4,
                            sb + ((stage + 4) % STG) * STAGE_B, tid);
        else
            CP_COMMIT();

        load_a_frags(slot + 32, aoff, fa1);
        load_b_frags(slot, boff, fb);

        mma_block(fa0, fb, acc);

        load_b_frags(slot + 32, boff, fb);

        if (stage + 1 < NSTAGE) {
            CP_WAIT(3);
            __syncthreads();
            load_a_frags(sb + ((stage + 1) % STG) * STAGE_B, aoff, fa0);
        }

        mma_block(fa1, fb, acc);
    }

    // epilogue
    const float* bp = bias0;
    __half* Hout = H0;
    int coloff = n0;
    if (n0 >= CC) { bp = bias1; Hout = H1; coloff = n0 - CC; }

    const int g = lane >> 2, tg = lane & 3;
#pragma unroll
    for (int mt = 0; mt < 2; ++mt) {
        int r0 = m0 + wm * 32 + mt * 16 + g;
#pragma unroll
        for (int nt = 0; nt < 8; ++nt) {
            int col = coloff + wn * 64 + nt * 8 + 2 * tg;
            float bx = bp[col], by = bp[col + 1];
#pragma unroll
            for (int half = 0; half < 2; ++half) {
                int row = r0 + half * 8;
                if (row < M) {
                    float vx = acc[mt][nt][half * 2]     + bx;
                    float vy = acc[mt][nt][half * 2 + 1] + by;
                    size_t o = (size_t)row * CC + col;
                    __half hx = __float2half(vx);
                    __half hy = __float2half(vy);
                    if (mode == 1) {
                        *(float2*)(Cf + o) = make_float2(vx, vy);
                        *(ushort2*)(H0 + o) = make_ushort2(*(unsigned short*)&hx, *(unsigned short*)&hy);
                    } else {
                        *(ushort2*)(Hout + o) = make_ushort2(*(unsigned short*)&hx, *(unsigned short*)&hy);
                    }
                }
            }
        }
    }
}

// ---------------- fused GATv2 attention + aggregate + residual + LN + GELU + convert ----------------
__global__ __launch_bounds__(256) void k_aggregate(
    const float* __restrict__ att, const float* __restrict__ gbias,
    const float* __restrict__ lnw, const float* __restrict__ lnb, int layer)
{
    const int v = blockIdx.x;
    const int tid = threadIdx.x;
    const int w = tid >> 5, lane = tid & 31;
    const int c0 = w * DD + lane;

    const float* attL = att + (size_t)layer * CC;
    float a0 = attL[c0], a1 = attL[c0 + 32], a2 = attL[c0 + 64];
    const __half* xrv = g_xrh + (size_t)v * CC;
    float r0 = __half2float(xrv[c0]);
    float r1 = __half2float(xrv[c0 + 32]);
    float r2 = __half2float(xrv[c0 + 64]);

    int e0 = g_off[v], e1 = g_off[v + 1];
    float m = -INFINITY, s = 0.f, acc0 = 0.f, acc1 = 0.f, acc2 = 0.f;

    for (int e = e0; e < e1; ++e) {
        int src = g_csrsrc[e];
        const __half* xv = g_xlh + (size_t)src * CC + c0;
        float v0 = __half2float(xv[0]);
        float v1 = __half2float(xv[32]);
        float v2 = __half2float(xv[64]);
        float t0 = v0 + r0; t0 = (t0 > 0.f) ? t0 : 0.2f * t0;
        float t1 = v1 + r1; t1 = (t1 > 0.f) ? t1 : 0.2f * t1;
        float t2 = v2 + r2; t2 = (t2 > 0.f) ? t2 : 0.2f * t2;
        float p = t0 * a0 + t1 * a1 + t2 * a2;
#pragma unroll
        for (int o = 16; o > 0; o >>= 1) p += __shfl_xor_sync(0xffffffffu, p, o);
        float mn = fmaxf(m, p);
        float corr = __expf(m - mn);
        float wt = __expf(p - mn);
        s = s * corr + wt;
        acc0 = acc0 * corr + wt * v0;
        acc1 = acc1 * corr + wt * v1;
        acc2 = acc2 * corr + wt * v2;
        m = mn;
    }

    float inv = 1.f / s;
    const float* gb = gbias + (size_t)layer * CC;
    const float* hv = g_h + (size_t)v * CC;
    float t0 = acc0 * inv + gb[c0]      + hv[c0];
    float t1 = acc1 * inv + gb[c0 + 32] + hv[c0 + 32];
    float t2 = acc2 * inv + gb[c0 + 64] + hv[c0 + 64];

    float ls = t0 + t1 + t2;
    float lq = t0 * t0 + t1 * t1 + t2 * t2;
#pragma unroll
    for (int o = 16; o > 0; o >>= 1) {
        ls += __shfl_xor_sync(0xffffffffu, ls, o);
        lq += __shfl_xor_sync(0xffffffffu, lq, o);
    }
    __shared__ float shs[8], shq[8];
    if (lane == 0) { shs[w] = ls; shq[w] = lq; }
    __syncthreads();
    float S = 0.f, Q = 0.f;
#pragma unroll
    for (int i = 0; i < 8; ++i) { S += shs[i]; Q += shq[i]; }
    float mu = S * (1.f / 768.f);
    float var = Q * (1.f / 768.f) - mu * mu;
    float rs = rsqrtf(var + 1e-5f);

    const float* lw = lnw + (size_t)layer * CC;
    const float* lb = lnb + (size_t)layer * CC;
    float y0 = (t0 - mu) * rs * lw[c0]      + lb[c0];
    float y1 = (t1 - mu) * rs * lw[c0 + 32] + lb[c0 + 32];
    float y2 = (t2 - mu) * rs * lw[c0 + 64] + lb[c0 + 64];

    float gA = 0.5f * y0 * (1.f + erff(y0 * 0.70710678118654752f));
    float gB = 0.5f * y1 * (1.f + erff(y1 * 0.70710678118654752f));
    float gC = 0.5f * y2 * (1.f + erff(y2 * 0.70710678118654752f));

    float* hw = g_h + (size_t)v * CC;
    hw[c0] = gA; hw[c0 + 32] = gB; hw[c0 + 64] = gC;

    size_t ob = (size_t)v * CC;
    g_bh[ob + c0]      = __float2half(gA);
    g_bh[ob + c0 + 32] = __float2half(gB);
    g_bh[ob + c0 + 64] = __float2half(gC);
}

// ---------------- per-layer mean pool over graphs (reads g_h) ----------------
__global__ __launch_bounds__(256) void k_pool_layer(int layer) {
    int g = blockIdx.x;
    int part = blockIdx.y;         // 0..2 -> 256-col slab
    int t = threadIdx.x;
    int col = part * 256 + t;
    int s0 = g_gstart[g], s1 = g_gstart[g + 1];
    float a = 0.f;
    for (int i = s0; i < s1; ++i)
        a += g_h[(size_t)i * CC + col];
    float inv = 1.f / fmaxf((float)(s1 - s0), 1.f);
    g_pooled[(size_t)g * C3 + (size_t)layer * CC + col] = a * inv;
}

// ---------------- output LN + classifier ----------------
__global__ __launch_bounds__(256) void k_final(
    const float* __restrict__ lnw, const float* __restrict__ lnb,
    const float* __restrict__ wout, const float* __restrict__ bout,
    float* __restrict__ out)
{
    __shared__ float row[C3];
    __shared__ float red_s[8], red_q[8];
    __shared__ float sh_mu, sh_rs;
    int g = blockIdx.x, t = threadIdx.x;
    int lane = t & 31, w = t >> 5;

    float s = 0.f, q = 0.f;
    for (int c = t; c < C3; c += 256) {
        float v = g_pooled[(size_t)g * C3 + c];
        row[c] = v;
        s += v;
        q += v * v;
    }
#pragma unroll
    for (int o = 16; o > 0; o >>= 1) {
        s += __shfl_xor_sync(0xffffffffu, s, o);
        q += __shfl_xor_sync(0xffffffffu, q, o);
    }
    if (lane == 0) { red_s[w] = s; red_q[w] = q; }
    __syncthreads();
    if (t == 0) {
        float S = 0.f, Q = 0.f;
#pragma unroll
        for (int i = 0; i < 8; ++i) { S += red_s[i]; Q += red_q[i]; }
        float mu = S * (1.f / (float)C3);
        float var = Q * (1.f / (float)C3) - mu * mu;
        sh_mu = mu;
        sh_rs = rsqrtf(var + 1e-5f);
    }
    __syncthreads();
    float mu = sh_mu, rs = sh_rs;
    for (int c = t; c < C3; c += 256)
        row[c] = (row[c] - mu) * rs * lnw[c] + lnb[c];
    __syncthreads();

    for (int cls = w; cls < NCLS; cls += 8) {
        float p = 0.f;
        for (int i = lane; i < C3; i += 32)
            p += row[i] * wout[(size_t)i * NCLS + cls];
#pragma unroll
        for (int o = 16; o > 0; o >>= 1) p += __shfl_xor_sync(0xffffffffu, p, o);
        if (lane == 0) out[(size_t)g * NCLS + cls] = p + bout[cls];
    }
}

// ---------------- launch ----------------
extern "C" void kernel_launch(void* const* d_in, const int* in_sizes, int n_in,
                              void* d_out, int out_size)
{
    const float* x        = (const float*)d_in[0];
    const void*  eraw     = d_in[1];
    const void*  braw     = d_in[2];
    const float* w_in     = (const float*)d_in[3];
    const float* b_in     = (const float*)d_in[4];
    const float* Wl       = (const float*)d_in[5];
    const float* bl       = (const float*)d_in[6];
    const float* Wr       = (const float*)d_in[7];
    const float* br       = (const float*)d_in[8];
    const float* att      = (const float*)d_in[9];
    const float* gat_bias = (const float*)d_in[10];
    const float* ln_w     = (const float*)d_in[11];
    const float* ln_b     = (const float*)d_in[12];
    const float* out_ln_w = (const float*)d_in[13];
    const float* out_ln_b = (const float*)d_in[14];
    const float* w_out    = (const float*)d_in[15];
    const float* b_out    = (const float*)d_in[16];
    float* out = (float*)d_out;

    float *ph;
    __half *pah, *pbh, *pxlh, *pxrh, *pw;
    cudaGetSymbolAddress((void**)&ph,   g_h);
    cudaGetSymbolAddress((void**)&pah,  g_ah);
    cudaGetSymbolAddress((void**)&pbh,  g_bh);
    cudaGetSymbolAddress((void**)&pxlh, g_xlh);
    cudaGetSymbolAddress((void**)&pxrh, g_xrh);
    cudaGetSymbolAddress((void**)&pw,   g_wT);

    static int smem_set = 0;
    if (!smem_set) {
        cudaFuncSetAttribute(k_gemm_mma, cudaFuncAttributeMaxDynamicSharedMemorySize, GEMM_SMEM);
        smem_set = 1;
    }

    const int splitg = (NN * CC / 4 + 255) / 256;
    dim3 ggrid1(6, (NN + 127) / 128);    // input gemm: 768 cols / 128
    dim3 ggrid2(12, (NN + 127) / 128);   // fused Wl|Wr gemm: 1536 cols / 128

    // front-load so the profiler slot lands on the GEMM
    k_transpose<<<dim3(24, 24, 7), dim3(32, 32)>>>(w_in, Wl, Wr);
    k_split_x<<<splitg, 256>>>(x);
    k_detect<<<1, 1>>>(eraw);
    k_gemm_mma<<<ggrid1, 256, GEMM_SMEM>>>(pah, pw, b_in, b_in, ph, pbh, pbh, NN, 1);

    // CSR build
    k_prep<<<(NN + 255) / 256, 256>>>();
    k_convert_count<<<(EE + 255) / 256, 256>>>(eraw, braw);
    k_chsum<<<SCAN_NCH, 1024>>>();
    k_choff<<<1, 32>>>();
    k_offsets<<<SCAN_NCH, 1024>>>();
    k_csrfill<<<(EE + 255) / 256, 256>>>();
    k_gstart<<<(NN + 256) / 256, 256>>>();

    for (int l = 0; l < 3; ++l) {
        const __half* BW = pw + (size_t)(1 + 2 * l) * CC * CC;   // Wl then Wr adjacent
        k_gemm_mma<<<ggrid2, 256, GEMM_SMEM>>>(pbh, BW,
                                               bl + (size_t)l * CC, br + (size_t)l * CC,
                                               nullptr, pxlh, pxrh, NN, 2);
        k_aggregate<<<NN, 256>>>(att, gat_bias, ln_w, ln_b, l);
        k_pool_layer<<<dim3(GG, 3), 256>>>(l);
    }

    k_final<<<GG, 256>>>(out_ln_w, out_ln_b, w_out, b_out, out);

    (void)in_sizes; (void)n_in; (void)out_size;
}

// round 14
// speedup vs baseline: 1.0370x; 1.0244x over previous
#include <cuda_runtime.h>
#include <cuda_fp16.h>
#include <math.h>
#include <stdint.h>

// ---------------- problem constants ----------------
#define NN 20000
#define EE 160000
#define CC 768
#define HH 8
#define DD 96
#define GG 256
#define NCLS 32
#define C3 (3*CC)
#define ETOT (EE+NN)

// ---------------- device scratch (static, no allocs) ----------------
__device__ float g_h[(size_t)NN*CC];
__device__ float g_pooled[(size_t)GG*C3];

__device__ __half g_xlh[(size_t)NN*CC];  // fp16 xl (layer gemm out)
__device__ __half g_xrh[(size_t)NN*CC];  // fp16 xr (layer gemm out)
__device__ __half g_ah[(size_t)NN*CC];   // fp16 of x (input gemm A)
__device__ __half g_bh[(size_t)NN*CC];   // fp16 of h (layer gemm A)
__device__ __half g_jh[(size_t)NN*C3];   // fp16 JumpingKnowledge buffer
__device__ __half g_wT[(size_t)7*CC*CC]; // fp16 transposed weights [gemm][N][K]

__device__ int g_src[EE];
__device__ int g_dst[EE];
__device__ int g_batchi[NN];
__device__ int g_cnt[NN];
__device__ int g_cur[NN];
__device__ int g_off[NN+1];
__device__ int g_csrsrc[ETOT];
#define SCAN_NCH 20
__device__ int g_chsum[SCAN_NCH];
__device__ int g_choff[SCAN_NCH];
__device__ int g_gstart[GG+1];
__device__ int g_is64;

// ---------------- PTX helpers (plain sm_80-era PTX only) ----------------
__device__ __forceinline__ uint32_t smem_u32(const void* p) {
    uint32_t a;
    asm("{ .reg .u64 t; cvta.to.shared.u64 t, %1; cvt.u32.u64 %0, t; }" : "=r"(a) : "l"(p));
    return a;
}
__device__ __forceinline__ void cpa16(uint32_t dst, const void* src) {
    asm volatile("cp.async.cg.shared.global [%0], [%1], 16;" :: "r"(dst), "l"(src));
}
#define CP_COMMIT() asm volatile("cp.async.commit_group;" ::: "memory")
#define CP_WAIT(n)  asm volatile("cp.async.wait_group %0;" ::"n"(n):"memory")

__device__ __forceinline__ void ldm_x4(uint32_t& r0, uint32_t& r1, uint32_t& r2, uint32_t& r3, uint32_t addr) {
    asm volatile("ldmatrix.sync.aligned.m8n8.x4.shared.b16 {%0,%1,%2,%3}, [%4];"
                 : "=r"(r0), "=r"(r1), "=r"(r2), "=r"(r3) : "r"(addr));
}
__device__ __forceinline__ void mma16816(float& c0, float& c1, float& c2, float& c3,
                                         uint32_t a0, uint32_t a1, uint32_t a2, uint32_t a3,
                                         uint32_t b0, uint32_t b1) {
    asm volatile("mma.sync.aligned.m16n8k16.row.col.f32.f16.f16.f32 "
                 "{%0,%1,%2,%3},{%4,%5,%6,%7},{%8,%9},{%0,%1,%2,%3};"
                 : "+f"(c0), "+f"(c1), "+f"(c2), "+f"(c3)
                 : "r"(a0), "r"(a1), "r"(a2), "r"(a3), "r"(b0), "r"(b1));
}

// ---------------- weight transpose to fp16: g_wT[g][n][k] = fp16(W_g[k][n]) ----------------
__global__ __launch_bounds__(1024) void k_transpose(
    const float* __restrict__ w_in, const float* __restrict__ Wl, const float* __restrict__ Wr)
{
    __shared__ float t[32][33];
    int g = blockIdx.z;
    const float* src;
    if (g == 0) src = w_in;
    else {
        int l = (g - 1) >> 1;
        src = (((g - 1) & 1) == 0 ? Wl : Wr) + (size_t)l * CC * CC;
    }
    int x = blockIdx.x * 32 + threadIdx.x;   // n
    int y = blockIdx.y * 32 + threadIdx.y;   // k
    t[threadIdx.y][threadIdx.x] = src[(size_t)y * CC + x];
    __syncthreads();
    int on = blockIdx.x * 32 + threadIdx.y;
    int ok = blockIdx.y * 32 + threadIdx.x;
    g_wT[(size_t)g * CC * CC + (size_t)on * CC + ok] = __float2half(t[threadIdx.x][threadIdx.y]);
}

// ---------------- fp16 convert of x ----------------
__global__ __launch_bounds__(256) void k_split_x(const float* __restrict__ in) {
    int i = blockIdx.x * blockDim.x + threadIdx.x;
    if (i >= NN * CC / 4) return;
    float4 v = *(const float4*)(in + (size_t)i * 4);
    __half h0 = __float2half(v.x), h1 = __float2half(v.y);
    __half h2 = __float2half(v.z), h3 = __float2half(v.w);
    ushort4 hv = make_ushort4(*(unsigned short*)&h0, *(unsigned short*)&h1,
                              *(unsigned short*)&h2, *(unsigned short*)&h3);
    *(ushort4*)(g_ah + (size_t)i * 4) = hv;
}

// ---------------- index dtype detection + CSR build ----------------
__global__ void k_detect(const void* eraw) {
    const unsigned int* p = (const unsigned int*)eraw;
    unsigned int acc = 0;
#pragma unroll
    for (int j = 0; j < 8; ++j) acc |= p[2*j + 1];
    g_is64 = (acc == 0u) ? 1 : 0;
}

__global__ void k_prep() {
    int i = blockIdx.x * blockDim.x + threadIdx.x;
    if (i < NN) { g_cnt[i] = 1; g_cur[i] = 1; }
}

__global__ void k_convert_count(const void* eraw, const void* braw) {
    int i = blockIdx.x * blockDim.x + threadIdx.x;
    int is64 = g_is64;
    if (i < EE) {
        int s, d;
        if (is64) {
            const long long* p = (const long long*)eraw;
            s = (int)p[i]; d = (int)p[EE + i];
        } else {
            const int* p = (const int*)eraw;
            s = p[i]; d = p[EE + i];
        }
        g_src[i] = s; g_dst[i] = d;
        atomicAdd(&g_cnt[d], 1);
    }
    if (i < NN) {
        if (is64) {
            const long long* p = (const long long*)braw;
            g_batchi[i] = (int)p[i];
        } else {
            const int* p = (const int*)braw;
            g_batchi[i] = p[i];
        }
    }
}

__global__ __launch_bounds__(1024) void k_chsum() {
    __shared__ int sh[1024];
    int t = threadIdx.x;
    int i = blockIdx.x * 1024 + t;
    sh[t] = (i < NN) ? g_cnt[i] : 0;
    __syncthreads();
    for (int o = 512; o > 0; o >>= 1) {
        if (t < o) sh[t] += sh[t + o];
        __syncthreads();
    }
    if (t == 0) g_chsum[blockIdx.x] = sh[0];
}

__global__ void k_choff() {
    if (threadIdx.x == 0 && blockIdx.x == 0) {
        int run = 0;
        for (int i = 0; i < SCAN_NCH; ++i) { g_choff[i] = run; run += g_chsum[i]; }
        g_off[NN] = run;
    }
}

__global__ __launch_bounds__(1024) void k_offsets() {
    __shared__ int sh[1024];
    int t = threadIdx.x;
    int i = blockIdx.x * 1024 + t;
    int v = (i < NN) ? g_cnt[i] : 0;
    sh[t] = v;
    __syncthreads();
#pragma unroll
    for (int o = 1; o < 1024; o <<= 1) {
        int add = (t >= o) ? sh[t - o] : 0;
        __syncthreads();
        sh[t] += add;
        __syncthreads();
    }
    if (i < NN) g_off[i] = sh[t] - v + g_choff[blockIdx.x];
}

__global__ void k_csrfill() {
    int i = blockIdx.x * blockDim.x + threadIdx.x;
    if (i < NN) g_csrsrc[g_off[i]] = i;
    if (i < EE) {
        int d = g_dst[i];
        int slot = g_off[d] + atomicAdd(&g_cur[d], 1);
        g_csrsrc[slot] = g_src[i];
    }
}

__global__ void k_gstart() {
    int i = blockIdx.x * blockDim.x + threadIdx.x;
    if (i == 0) {
        int b = g_batchi[0];
        for (int g = 0; g <= b; ++g) g_gstart[g] = 0;
    } else if (i < NN) {
        int b0 = g_batchi[i - 1], b1 = g_batchi[i];
        for (int g = b0 + 1; g <= b1; ++g) g_gstart[g] = i;
    } else if (i == NN) {
        int b = g_batchi[NN - 1];
        for (int g = b + 1; g <= GG; ++g) g_gstart[g] = NN;
    }
}

// ---------------- fp16 single-pass tensor-core GEMM (128x128 tile, 2 CTAs/SM) ----------------
#define ROWB 80                 // 64B data + 16B pad
#define TILE_A 10240            // 128 rows * 80B
#define STAGE_B 20480           // A + B (128 rows each)
#define STG 5
#define GEMM_SMEM (STG*STAGE_B) // 102.4 KB -> 2 CTAs/SM
#define NSTAGE 24               // 768 / 32

__device__ __forceinline__ void gemm_load_stage(
    const __half* __restrict__ Ah, const __half* __restrict__ Bh,
    int m0, int n0, int M, int kblk, uint32_t sb, int tid)
{
#pragma unroll
    for (int i = 0; i < 4; ++i) {
        int q = tid + i * 256;        // 0..1023
        int row = q >> 2, ch = q & 3;
        if (row < 128) {
            int ar = m0 + row; ar = (ar < M) ? ar : (M - 1);
            cpa16(sb + (uint32_t)(row * ROWB + ch * 16),
                  Ah + (size_t)ar * CC + kblk * 32 + ch * 8);
        } else {
            int br = row - 128;
            cpa16(sb + TILE_A + (uint32_t)(br * ROWB + ch * 16),
                  Bh + (size_t)(n0 + br) * CC + kblk * 32 + ch * 8);
        }
    }
    CP_COMMIT();
}

__device__ __forceinline__ void load_a_frags(uint32_t stg, uint32_t aoff, uint32_t* fa) {
    ldm_x4(fa[0], fa[1], fa[2], fa[3], stg + aoff);
    ldm_x4(fa[4], fa[5], fa[6], fa[7], stg + aoff + 16 * ROWB);
}
__device__ __forceinline__ void load_b_frags(uint32_t stg, uint32_t boff, uint32_t* fb) {
#pragma unroll
    for (int nc = 0; nc < 4; ++nc)
        ldm_x4(fb[nc*4+0], fb[nc*4+1], fb[nc*4+2], fb[nc*4+3],
               stg + TILE_A + boff + nc * 16 * ROWB);
}

__device__ __forceinline__ void mma_block(const uint32_t* fa, const uint32_t* fb,
                                          float acc[2][8][4])
{
#pragma unroll
    for (int nc = 0; nc < 4; ++nc) {
#pragma unroll
        for (int sub = 0; sub < 2; ++sub) {
            int nt = nc * 2 + sub;
            uint32_t b0 = fb[nc * 4 + sub * 2], b1 = fb[nc * 4 + sub * 2 + 1];
            mma16816(acc[0][nt][0], acc[0][nt][1], acc[0][nt][2], acc[0][nt][3],
                     fa[0], fa[1], fa[2], fa[3], b0, b1);
            mma16816(acc[1][nt][0], acc[1][nt][1], acc[1][nt][2], acc[1][nt][3],
                     fa[4], fa[5], fa[6], fa[7], b0, b1);
        }
    }
}

// mode 1 (input gemm): write fp32 Cf + fp16 g_bh.  mode 2 (layer gemm): write fp16 H0/H1 only.
__global__ __launch_bounds__(256, 2) void k_gemm_mma(
    const __half* __restrict__ Ah, const __half* __restrict__ Bh,
    const float* __restrict__ bias0, const float* __restrict__ bias1,
    float* __restrict__ Cf, __half* __restrict__ H0, __half* __restrict__ H1,
    int M, int mode)
{
    extern __shared__ char smraw[];
    uint32_t sb = smem_u32(smraw);
    const int tid = threadIdx.x;
    const int wid = tid >> 5, lane = tid & 31;
    const int wm = wid >> 1, wn = wid & 1;          // 4 x 2 warps -> 128 x 128
    const int n0 = blockIdx.x * 128, m0 = blockIdx.y * 128;

    const int arow = lane & 15;
    const uint32_t aoff = (uint32_t)((wm * 32 + arow) * ROWB + (lane >> 4) * 16);
    const int brow = (lane & 7) | ((lane >> 4) << 3);
    const uint32_t boff = (uint32_t)((wn * 64 + brow) * ROWB + ((lane >> 3) & 1) * 16);

    float acc[2][8][4];
#pragma unroll
    for (int a = 0; a < 2; ++a)
#pragma unroll
        for (int b = 0; b < 8; ++b)
#pragma unroll
            for (int c = 0; c < 4; ++c) acc[a][b][c] = 0.f;

    uint32_t fa0[8], fa1[8];   // A double-buffered
    uint32_t fb[16];           // B single-buffered

#pragma unroll
    for (int s = 0; s < 4; ++s)
        gemm_load_stage(Ah, Bh, m0, n0, M, s, sb + s * STAGE_B, tid);
    CP_WAIT(3);
    __syncthreads();
    load_a_frags(sb, aoff, fa0);

    for (int stage = 0; stage < NSTAGE; ++stage) {
        uint32_t slot = sb + (stage % STG) * STAGE_B;

        if (stage + 4 < NSTAGE)
            gemm_load_stage(Ah, Bh, m0, n0, M, stage + 4,
                            sb + ((stage + 4) % STG) * STAGE_B, tid);
        else
            CP_COMMIT();

        load_a_frags(slot + 32, aoff, fa1);
        load_b_frags(slot, boff, fb);

        mma_block(fa0, fb, acc);

        load_b_frags(slot + 32, boff, fb);

        if (stage + 1 < NSTAGE) {
            CP_WAIT(3);
            __syncthreads();
            load_a_frags(sb + ((stage + 1) % STG) * STAGE_B, aoff, fa0);
        }

        mma_block(fa1, fb, acc);
    }

    // epilogue
    const float* bp = bias0;
    __half* Hout = H0;
    int coloff = n0;
    if (n0 >= CC) { bp = bias1; Hout = H1; coloff = n0 - CC; }

    const int g = lane >> 2, tg = lane & 3;
#pragma unroll
    for (int mt = 0; mt < 2; ++mt) {
        int r0 = m0 + wm * 32 + mt * 16 + g;
#pragma unroll
        for (int nt = 0; nt < 8; ++nt) {
            int col = coloff + wn * 64 + nt * 8 + 2 * tg;
            float bx = bp[col], by = bp[col + 1];
#pragma unroll
            for (int half = 0; half < 2; ++half) {
                int row = r0 + half * 8;
                if (row < M) {
                    float vx = acc[mt][nt][half * 2]     + bx;
                    float vy = acc[mt][nt][half * 2 + 1] + by;
                    size_t o = (size_t)row * CC + col;
                    __half hx = __float2half(vx);
                    __half hy = __float2half(vy);
                    if (mode == 1) {
                        *(float2*)(Cf + o) = make_float2(vx, vy);
                        *(ushort2*)(H0 + o) = make_ushort2(*(unsigned short*)&hx, *(unsigned short*)&hy);
                    } else {
                        *(ushort2*)(Hout + o) = make_ushort2(*(unsigned short*)&hx, *(unsigned short*)&hy);
                    }
                }
            }
        }
    }
}

// ---------------- fused GATv2 attention + aggregate + residual + LN + GELU + converts ----------------
__global__ __launch_bounds__(256) void k_aggregate(
    const float* __restrict__ att, const float* __restrict__ gbias,
    const float* __restrict__ lnw, const float* __restrict__ lnb, int layer)
{
    const int v = blockIdx.x;
    const int tid = threadIdx.x;
    const int w = tid >> 5, lane = tid & 31;
    const int c0 = w * DD + lane;

    const float* attL = att + (size_t)layer * CC;
    float a0 = attL[c0], a1 = attL[c0 + 32], a2 = attL[c0 + 64];
    const __half* xrv = g_xrh + (size_t)v * CC;
    float r0 = __half2float(xrv[c0]);
    float r1 = __half2float(xrv[c0 + 32]);
    float r2 = __half2float(xrv[c0 + 64]);

    int e0 = g_off[v], e1 = g_off[v + 1];
    float m = -INFINITY, s = 0.f, acc0 = 0.f, acc1 = 0.f, acc2 = 0.f;

    for (int e = e0; e < e1; ++e) {
        int src = g_csrsrc[e];
        const __half* xv = g_xlh + (size_t)src * CC + c0;
        float v0 = __half2float(xv[0]);
        float v1 = __half2float(xv[32]);
        float v2 = __half2float(xv[64]);
        float t0 = v0 + r0; t0 = (t0 > 0.f) ? t0 : 0.2f * t0;
        float t1 = v1 + r1; t1 = (t1 > 0.f) ? t1 : 0.2f * t1;
        float t2 = v2 + r2; t2 = (t2 > 0.f) ? t2 : 0.2f * t2;
        float p = t0 * a0 + t1 * a1 + t2 * a2;
#pragma unroll
        for (int o = 16; o > 0; o >>= 1) p += __shfl_xor_sync(0xffffffffu, p, o);
        float mn = fmaxf(m, p);
        float corr = __expf(m - mn);
        float wt = __expf(p - mn);
        s = s * corr + wt;
        acc0 = acc0 * corr + wt * v0;
        acc1 = acc1 * corr + wt * v1;
        acc2 = acc2 * corr + wt * v2;
        m = mn;
    }

    float inv = 1.f / s;
    const float* gb = gbias + (size_t)layer * CC;
    const float* hv = g_h + (size_t)v * CC;
    float t0 = acc0 * inv + gb[c0]      + hv[c0];
    float t1 = acc1 * inv + gb[c0 + 32] + hv[c0 + 32];
    float t2 = acc2 * inv + gb[c0 + 64] + hv[c0 + 64];

    float ls = t0 + t1 + t2;
    float lq = t0 * t0 + t1 * t1 + t2 * t2;
#pragma unroll
    for (int o = 16; o > 0; o >>= 1) {
        ls += __shfl_xor_sync(0xffffffffu, ls, o);
        lq += __shfl_xor_sync(0xffffffffu, lq, o);
    }
    __shared__ float shs[8], shq[8];
    if (lane == 0) { shs[w] = ls; shq[w] = lq; }
    __syncthreads();
    float S = 0.f, Q = 0.f;
#pragma unroll
    for (int i = 0; i < 8; ++i) { S += shs[i]; Q += shq[i]; }
    float mu = S * (1.f / 768.f);
    float var = Q * (1.f / 768.f) - mu * mu;
    float rs = rsqrtf(var + 1e-5f);

    const float* lw = lnw + (size_t)layer * CC;
    const float* lb = lnb + (size_t)layer * CC;
    float y0 = (t0 - mu) * rs * lw[c0]      + lb[c0];
    float y1 = (t1 - mu) * rs * lw[c0 + 32] + lb[c0 + 32];
    float y2 = (t2 - mu) * rs * lw[c0 + 64] + lb[c0 + 64];

    float gA = 0.5f * y0 * (1.f + erff(y0 * 0.70710678118654752f));
    float gB = 0.5f * y1 * (1.f + erff(y1 * 0.70710678118654752f));
    float gC = 0.5f * y2 * (1.f + erff(y2 * 0.70710678118654752f));

    float* hw = g_h + (size_t)v * CC;
    hw[c0] = gA; hw[c0 + 32] = gB; hw[c0 + 64] = gC;

    __half hA = __float2half(gA), hB = __float2half(gB), hC = __float2half(gC);

    size_t ob = (size_t)v * CC;
    g_bh[ob + c0]      = hA;
    g_bh[ob + c0 + 32] = hB;
    g_bh[ob + c0 + 64] = hC;

    __half* jw = g_jh + (size_t)v * C3 + (size_t)layer * CC;
    jw[c0]      = hA;
    jw[c0 + 32] = hB;
    jw[c0 + 64] = hC;
}

// ---------------- fused mean pool over graphs (reads fp16 JK buffer) ----------------
__global__ __launch_bounds__(256) void k_pool() {
    int g = blockIdx.x;
    int part = blockIdx.y;          // 0..2 -> layer slab
    int t = threadIdx.x;
    int s0 = g_gstart[g], s1 = g_gstart[g + 1];
    float a0 = 0.f, a1 = 0.f, a2 = 0.f;
    for (int i = s0; i < s1; ++i) {
        const __half* r = g_jh + (size_t)i * C3 + (size_t)part * CC;
        a0 += __half2float(r[t]);
        a1 += __half2float(r[t + 256]);
        a2 += __half2float(r[t + 512]);
    }
    float inv = 1.f / fmaxf((float)(s1 - s0), 1.f);
    float* o = g_pooled + (size_t)g * C3 + (size_t)part * CC;
    o[t]       = a0 * inv;
    o[t + 256] = a1 * inv;
    o[t + 512] = a2 * inv;
}

// ---------------- output LN + classifier ----------------
__global__ __launch_bounds__(256) void k_final(
    const float* __restrict__ lnw, const float* __restrict__ lnb,
    const float* __restrict__ wout, const float* __restrict__ bout,
    float* __restrict__ out)
{
    __shared__ float row[C3];
    __shared__ float red_s[8], red_q[8];
    __shared__ float sh_mu, sh_rs;
    int g = blockIdx.x, t = threadIdx.x;
    int lane = t & 31, w = t >> 5;

    float s = 0.f, q = 0.f;
    for (int c = t; c < C3; c += 256) {
        float v = g_pooled[(size_t)g * C3 + c];
        row[c] = v;
        s += v;
        q += v * v;
    }
#pragma unroll
    for (int o = 16; o > 0; o >>= 1) {
        s += __shfl_xor_sync(0xffffffffu, s, o);
        q += __shfl_xor_sync(0xffffffffu, q, o);
    }
    if (lane == 0) { red_s[w] = s; red_q[w] = q; }
    __syncthreads();
    if (t == 0) {
        float S = 0.f, Q = 0.f;
#pragma unroll
        for (int i = 0; i < 8; ++i) { S += red_s[i]; Q += red_q[i]; }
        float mu = S * (1.f / (float)C3);
        float var = Q * (1.f / (float)C3) - mu * mu;
        sh_mu = mu;
        sh_rs = rsqrtf(var + 1e-5f);
    }
    __syncthreads();
    float mu = sh_mu, rs = sh_rs;
    for (int c = t; c < C3; c += 256)
        row[c] = (row[c] - mu) * rs * lnw[c] + lnb[c];
    __syncthreads();

    for (int cls = w; cls < NCLS; cls += 8) {
        float p = 0.f;
        for (int i = lane; i < C3; i += 32)
            p += row[i] * wout[(size_t)i * NCLS + cls];
#pragma unroll
        for (int o = 16; o > 0; o >>= 1) p += __shfl_xor_sync(0xffffffffu, p, o);
        if (lane == 0) out[(size_t)g * NCLS + cls] = p + bout[cls];
    }
}

// ---------------- launch ----------------
extern "C" void kernel_launch(void* const* d_in, const int* in_sizes, int n_in,
                              void* d_out, int out_size)
{
    const float* x        = (const float*)d_in[0];
    const void*  eraw     = d_in[1];
    const void*  braw     = d_in[2];
    const float* w_in     = (const float*)d_in[3];
    const float* b_in     = (const float*)d_in[4];
    const float* Wl       = (const float*)d_in[5];
    const float* bl       = (const float*)d_in[6];
    const float* Wr       = (const float*)d_in[7];
    const float* br       = (const float*)d_in[8];
    const float* att      = (const float*)d_in[9];
    const float* gat_bias = (const float*)d_in[10];
    const float* ln_w     = (const float*)d_in[11];
    const float* ln_b     = (const float*)d_in[12];
    const float* out_ln_w = (const float*)d_in[13];
    const float* out_ln_b = (const float*)d_in[14];
    const float* w_out    = (const float*)d_in[15];
    const float* b_out    = (const float*)d_in[16];
    float* out = (float*)d_out;

    float *ph;
    __half *pah, *pbh, *pxlh, *pxrh, *pw;
    cudaGetSymbolAddress((void**)&ph,   g_h);
    cudaGetSymbolAddress((void**)&pah,  g_ah);
    cudaGetSymbolAddress((void**)&pbh,  g_bh);
    cudaGetSymbolAddress((void**)&pxlh, g_xlh);
    cudaGetSymbolAddress((void**)&pxrh, g_xrh);
    cudaGetSymbolAddress((void**)&pw,   g_wT);

    static int smem_set = 0;
    if (!smem_set) {
        cudaFuncSetAttribute(k_gemm_mma, cudaFuncAttributeMaxDynamicSharedMemorySize, GEMM_SMEM);
        smem_set = 1;
    }

    const int splitg = (NN * CC / 4 + 255) / 256;
    dim3 ggrid1(6, (NN + 127) / 128);    // input gemm: 768 cols / 128
    dim3 ggrid2(12, (NN + 127) / 128);   // fused Wl|Wr gemm: 1536 cols / 128

    // front-load so the profiler slot lands on the GEMM
    k_transpose<<<dim3(24, 24, 7), dim3(32, 32)>>>(w_in, Wl, Wr);
    k_split_x<<<splitg, 256>>>(x);
    k_detect<<<1, 1>>>(eraw);
    k_gemm_mma<<<ggrid1, 256, GEMM_SMEM>>>(pah, pw, b_in, b_in, ph, pbh, pbh, NN, 1);

    // CSR build
    k_prep<<<(NN + 255) / 256, 256>>>();
    k_convert_count<<<(EE + 255) / 256, 256>>>(eraw, braw);
    k_chsum<<<SCAN_NCH, 1024>>>();
    k_choff<<<1, 32>>>();
    k_offsets<<<SCAN_NCH, 1024>>>();
    k_csrfill<<<(EE + 255) / 256, 256>>>();
    k_gstart<<<(NN + 256) / 256, 256>>>();

    for (int l = 0; l < 3; ++l) {
        const __half* BW = pw + (size_t)(1 + 2 * l) * CC * CC;   // Wl then Wr adjacent
        k_gemm_mma<<<ggrid2, 256, GEMM_SMEM>>>(pbh, BW,
                                               bl + (size_t)l * CC, br + (size_t)l * CC,
                                               nullptr, pxlh, pxrh, NN, 2);
        k_aggregate<<<NN, 256>>>(att, gat_bias, ln_w, ln_b, l);
    }

    k_pool<<<dim3(GG, 3), 256>>>();
    k_final<<<GG, 256>>>(out_ln_w, out_ln_b, w_out, b_out, out);

    (void)in_sizes; (void)n_in; (void)out_size;
}

// round 15
// speedup vs baseline: 1.0552x; 1.0175x over previous
#include <cuda_runtime.h>
#include <cuda_fp16.h>
#include <math.h>
#include <stdint.h>

// ---------------- problem constants ----------------
#define NN 20000
#define EE 160000
#define CC 768
#define HH 8
#define DD 96
#define GG 256
#define NCLS 32
#define C3 (3*CC)
#define ETOT (EE+NN)

// ---------------- device scratch (static, no allocs) ----------------
__device__ float g_h[(size_t)NN*CC];
__device__ float g_pooled[(size_t)GG*C3];

__device__ __half g_xlh[(size_t)NN*CC];  // fp16 xl (layer gemm out)
__device__ __half g_xrh[(size_t)NN*CC];  // fp16 xr (layer gemm out)
__device__ __half g_ah[(size_t)NN*CC];   // fp16 of x (input gemm A)
__device__ __half g_bh[(size_t)NN*CC];   // fp16 of h (layer gemm A)
__device__ __half g_jh[(size_t)NN*C3];   // fp16 JumpingKnowledge buffer
__device__ __half g_wT[(size_t)7*CC*CC]; // fp16 transposed weights [gemm][N][K]

__device__ int g_src[EE];
__device__ int g_dst[EE];
__device__ int g_batchi[NN];
__device__ int g_cnt[NN];
__device__ int g_cur[NN];
__device__ int g_off[NN+1];
__device__ int g_csrsrc[ETOT];
#define SCAN_NCH 20
__device__ int g_chsum[SCAN_NCH];
__device__ int g_choff[SCAN_NCH];
__device__ int g_gstart[GG+1];
__device__ int g_is64;

// ---------------- side stream for CSR overlap (created pre-main) ----------------
struct StreamHolder {
    cudaStream_t sB;
    cudaEvent_t evF, evJ;
    StreamHolder() {
        cudaStreamCreateWithFlags(&sB, cudaStreamNonBlocking);
        cudaEventCreateWithFlags(&evF, cudaEventDisableTiming);
        cudaEventCreateWithFlags(&evJ, cudaEventDisableTiming);
    }
};
static StreamHolder g_sh;

// ---------------- PTX helpers (plain sm_80-era PTX only) ----------------
__device__ __forceinline__ uint32_t smem_u32(const void* p) {
    uint32_t a;
    asm("{ .reg .u64 t; cvta.to.shared.u64 t, %1; cvt.u32.u64 %0, t; }" : "=r"(a) : "l"(p));
    return a;
}
__device__ __forceinline__ void cpa16(uint32_t dst, const void* src) {
    asm volatile("cp.async.cg.shared.global [%0], [%1], 16;" :: "r"(dst), "l"(src));
}
#define CP_COMMIT() asm volatile("cp.async.commit_group;" ::: "memory")
#define CP_WAIT(n)  asm volatile("cp.async.wait_group %0;" ::"n"(n):"memory")

__device__ __forceinline__ void ldm_x4(uint32_t& r0, uint32_t& r1, uint32_t& r2, uint32_t& r3, uint32_t addr) {
    asm volatile("ldmatrix.sync.aligned.m8n8.x4.shared.b16 {%0,%1,%2,%3}, [%4];"
                 : "=r"(r0), "=r"(r1), "=r"(r2), "=r"(r3) : "r"(addr));
}
__device__ __forceinline__ void mma16816(float& c0, float& c1, float& c2, float& c3,
                                         uint32_t a0, uint32_t a1, uint32_t a2, uint32_t a3,
                                         uint32_t b0, uint32_t b1) {
    asm volatile("mma.sync.aligned.m16n8k16.row.col.f32.f16.f16.f32 "
                 "{%0,%1,%2,%3},{%4,%5,%6,%7},{%8,%9},{%0,%1,%2,%3};"
                 : "+f"(c0), "+f"(c1), "+f"(c2), "+f"(c3)
                 : "r"(a0), "r"(a1), "r"(a2), "r"(a3), "r"(b0), "r"(b1));
}

// ---------------- weight transpose to fp16: g_wT[g][n][k] = fp16(W_g[k][n]) ----------------
__global__ __launch_bounds__(1024) void k_transpose(
    const float* __restrict__ w_in, const float* __restrict__ Wl, const float* __restrict__ Wr)
{
    __shared__ float t[32][33];
    int g = blockIdx.z;
    const float* src;
    if (g == 0) src = w_in;
    else {
        int l = (g - 1) >> 1;
        src = (((g - 1) & 1) == 0 ? Wl : Wr) + (size_t)l * CC * CC;
    }
    int x = blockIdx.x * 32 + threadIdx.x;   // n
    int y = blockIdx.y * 32 + threadIdx.y;   // k
    t[threadIdx.y][threadIdx.x] = src[(size_t)y * CC + x];
    __syncthreads();
    int on = blockIdx.x * 32 + threadIdx.y;
    int ok = blockIdx.y * 32 + threadIdx.x;
    g_wT[(size_t)g * CC * CC + (size_t)on * CC + ok] = __float2half(t[threadIdx.x][threadIdx.y]);
}

// ---------------- fp16 convert of x ----------------
__global__ __launch_bounds__(256) void k_split_x(const float* __restrict__ in) {
    int i = blockIdx.x * blockDim.x + threadIdx.x;
    if (i >= NN * CC / 4) return;
    float4 v = *(const float4*)(in + (size_t)i * 4);
    __half h0 = __float2half(v.x), h1 = __float2half(v.y);
    __half h2 = __float2half(v.z), h3 = __float2half(v.w);
    ushort4 hv = make_ushort4(*(unsigned short*)&h0, *(unsigned short*)&h1,
                              *(unsigned short*)&h2, *(unsigned short*)&h3);
    *(ushort4*)(g_ah + (size_t)i * 4) = hv;
}

// ---------------- index dtype detection + CSR build ----------------
__global__ void k_detect(const void* eraw) {
    const unsigned int* p = (const unsigned int*)eraw;
    unsigned int acc = 0;
#pragma unroll
    for (int j = 0; j < 8; ++j) acc |= p[2*j + 1];
    g_is64 = (acc == 0u) ? 1 : 0;
}

__global__ void k_prep() {
    int i = blockIdx.x * blockDim.x + threadIdx.x;
    if (i < NN) { g_cnt[i] = 1; g_cur[i] = 1; }
}

__global__ void k_convert_count(const void* eraw, const void* braw) {
    int i = blockIdx.x * blockDim.x + threadIdx.x;
    int is64 = g_is64;
    if (i < EE) {
        int s, d;
        if (is64) {
            const long long* p = (const long long*)eraw;
            s = (int)p[i]; d = (int)p[EE + i];
        } else {
            const int* p = (const int*)eraw;
            s = p[i]; d = p[EE + i];
        }
        g_src[i] = s; g_dst[i] = d;
        atomicAdd(&g_cnt[d], 1);
    }
    if (i < NN) {
        if (is64) {
            const long long* p = (const long long*)braw;
            g_batchi[i] = (int)p[i];
        } else {
            const int* p = (const int*)braw;
            g_batchi[i] = p[i];
        }
    }
}

__global__ __launch_bounds__(1024) void k_chsum() {
    __shared__ int sh[1024];
    int t = threadIdx.x;
    int i = blockIdx.x * 1024 + t;
    sh[t] = (i < NN) ? g_cnt[i] : 0;
    __syncthreads();
    for (int o = 512; o > 0; o >>= 1) {
        if (t < o) sh[t] += sh[t + o];
        __syncthreads();
    }
    if (t == 0) g_chsum[blockIdx.x] = sh[0];
}

__global__ void k_choff() {
    if (threadIdx.x == 0 && blockIdx.x == 0) {
        int run = 0;
        for (int i = 0; i < SCAN_NCH; ++i) { g_choff[i] = run; run += g_chsum[i]; }
        g_off[NN] = run;
    }
}

__global__ __launch_bounds__(1024) void k_offsets() {
    __shared__ int sh[1024];
    int t = threadIdx.x;
    int i = blockIdx.x * 1024 + t;
    int v = (i < NN) ? g_cnt[i] : 0;
    sh[t] = v;
    __syncthreads();
#pragma unroll
    for (int o = 1; o < 1024; o <<= 1) {
        int add = (t >= o) ? sh[t - o] : 0;
        __syncthreads();
        sh[t] += add;
        __syncthreads();
    }
    if (i < NN) g_off[i] = sh[t] - v + g_choff[blockIdx.x];
}

__global__ void k_csrfill() {
    int i = blockIdx.x * blockDim.x + threadIdx.x;
    if (i < NN) g_csrsrc[g_off[i]] = i;
    if (i < EE) {
        int d = g_dst[i];
        int slot = g_off[d] + atomicAdd(&g_cur[d], 1);
        g_csrsrc[slot] = g_src[i];
    }
}

__global__ void k_gstart() {
    int i = blockIdx.x * blockDim.x + threadIdx.x;
    if (i == 0) {
        int b = g_batchi[0];
        for (int g = 0; g <= b; ++g) g_gstart[g] = 0;
    } else if (i < NN) {
        int b0 = g_batchi[i - 1], b1 = g_batchi[i];
        for (int g = b0 + 1; g <= b1; ++g) g_gstart[g] = i;
    } else if (i == NN) {
        int b = g_batchi[NN - 1];
        for (int g = b + 1; g <= GG; ++g) g_gstart[g] = NN;
    }
}

// ---------------- fp16 single-pass tensor-core GEMM (128x128 tile, 2 CTAs/SM) ----------------
#define ROWB 80                 // 64B data + 16B pad
#define TILE_A 10240            // 128 rows * 80B
#define STAGE_B 20480           // A + B (128 rows each)
#define STG 5
#define GEMM_SMEM (STG*STAGE_B) // 102.4 KB -> 2 CTAs/SM
#define NSTAGE 24               // 768 / 32

__device__ __forceinline__ void gemm_load_stage(
    const __half* __restrict__ Ah, const __half* __restrict__ Bh,
    int m0, int n0, int M, int kblk, uint32_t sb, int tid)
{
#pragma unroll
    for (int i = 0; i < 4; ++i) {
        int q = tid + i * 256;        // 0..1023
        int row = q >> 2, ch = q & 3;
        if (row < 128) {
            int ar = m0 + row; ar = (ar < M) ? ar : (M - 1);
            cpa16(sb + (uint32_t)(row * ROWB + ch * 16),
                  Ah + (size_t)ar * CC + kblk * 32 + ch * 8);
        } else {
            int br = row - 128;
            cpa16(sb + TILE_A + (uint32_t)(br * ROWB + ch * 16),
                  Bh + (size_t)(n0 + br) * CC + kblk * 32 + ch * 8);
        }
    }
    CP_COMMIT();
}

__device__ __forceinline__ void load_a_frags(uint32_t stg, uint32_t aoff, uint32_t* fa) {
    ldm_x4(fa[0], fa[1], fa[2], fa[3], stg + aoff);
    ldm_x4(fa[4], fa[5], fa[6], fa[7], stg + aoff + 16 * ROWB);
}
__device__ __forceinline__ void load_b_frags(uint32_t stg, uint32_t boff, uint32_t* fb) {
#pragma unroll
    for (int nc = 0; nc < 4; ++nc)
        ldm_x4(fb[nc*4+0], fb[nc*4+1], fb[nc*4+2], fb[nc*4+3],
               stg + TILE_A + boff + nc * 16 * ROWB);
}

__device__ __forceinline__ void mma_block(const uint32_t* fa, const uint32_t* fb,
                                          float acc[2][8][4])
{
#pragma unroll
    for (int nc = 0; nc < 4; ++nc) {
#pragma unroll
        for (int sub = 0; sub < 2; ++sub) {
            int nt = nc * 2 + sub;
            uint32_t b0 = fb[nc * 4 + sub * 2], b1 = fb[nc * 4 + sub * 2 + 1];
            mma16816(acc[0][nt][0], acc[0][nt][1], acc[0][nt][2], acc[0][nt][3],
                     fa[0], fa[1], fa[2], fa[3], b0, b1);
            mma16816(acc[1][nt][0], acc[1][nt][1], acc[1][nt][2], acc[1][nt][3],
                     fa[4], fa[5], fa[6], fa[7], b0, b1);
        }
    }
}

// mode 1 (input gemm): write fp32 Cf + fp16 g_bh.  mode 2 (layer gemm): write fp16 H0/H1 only.
__global__ __launch_bounds__(256, 2) void k_gemm_mma(
    const __half* __restrict__ Ah, const __half* __restrict__ Bh,
    const float* __restrict__ bias0, const float* __restrict__ bias1,
    float* __restrict__ Cf, __half* __restrict__ H0, __half* __restrict__ H1,
    int M, int mode)
{
    extern __shared__ char smraw[];
    uint32_t sb = smem_u32(smraw);
    const int tid = threadIdx.x;
    const int wid = tid >> 5, lane = tid & 31;
    const int wm = wid >> 1, wn = wid & 1;          // 4 x 2 warps -> 128 x 128
    const int n0 = blockIdx.x * 128, m0 = blockIdx.y * 128;

    const int arow = lane & 15;
    const uint32_t aoff = (uint32_t)((wm * 32 + arow) * ROWB + (lane >> 4) * 16);
    const int brow = (lane & 7) | ((lane >> 4) << 3);
    const uint32_t boff = (uint32_t)((wn * 64 + brow) * ROWB + ((lane >> 3) & 1) * 16);

    float acc[2][8][4];
#pragma unroll
    for (int a = 0; a < 2; ++a)
#pragma unroll
        for (int b = 0; b < 8; ++b)
#pragma unroll
            for (int c = 0; c < 4; ++c) acc[a][b][c] = 0.f;

    uint32_t fa0[8], fa1[8];   // A double-buffered
    uint32_t fb[16];           // B single-buffered

#pragma unroll
    for (int s = 0; s < 4; ++s)
        gemm_load_stage(Ah, Bh, m0, n0, M, s, sb + s * STAGE_B, tid);
    CP_WAIT(3);
    __syncthreads();
    load_a_frags(sb, aoff, fa0);

    for (int stage = 0; stage < NSTAGE; ++stage) {
        uint32_t slot = sb + (stage % STG) * STAGE_B;

        if (stage + 4 < NSTAGE)
            gemm_load_stage(Ah, Bh, m0, n0, M, stage + 4,
                            sb + ((stage + 4) % STG) * STAGE_B, tid);
        else
            CP_COMMIT();

        load_a_frags(slot + 32, aoff, fa1);
        load_b_frags(slot, boff, fb);

        mma_block(fa0, fb, acc);

        load_b_frags(slot + 32, boff, fb);

        if (stage + 1 < NSTAGE) {
            CP_WAIT(3);
            __syncthreads();
            load_a_frags(sb + ((stage + 1) % STG) * STAGE_B, aoff, fa0);
        }

        mma_block(fa1, fb, acc);
    }

    // epilogue
    const float* bp = bias0;
    __half* Hout = H0;
    int coloff = n0;
    if (n0 >= CC) { bp = bias1; Hout = H1; coloff = n0 - CC; }

    const int g = lane >> 2, tg = lane & 3;
#pragma unroll
    for (int mt = 0; mt < 2; ++mt) {
        int r0 = m0 + wm * 32 + mt * 16 + g;
#pragma unroll
        for (int nt = 0; nt < 8; ++nt) {
            int col = coloff + wn * 64 + nt * 8 + 2 * tg;
            float bx = bp[col], by = bp[col + 1];
#pragma unroll
            for (int half = 0; half < 2; ++half) {
                int row = r0 + half * 8;
                if (row < M) {
                    float vx = acc[mt][nt][half * 2]     + bx;
                    float vy = acc[mt][nt][half * 2 + 1] + by;
                    size_t o = (size_t)row * CC + col;
                    __half hx = __float2half(vx);
                    __half hy = __float2half(vy);
                    if (mode == 1) {
                        *(float2*)(Cf + o) = make_float2(vx, vy);
                        *(ushort2*)(H0 + o) = make_ushort2(*(unsigned short*)&hx, *(unsigned short*)&hy);
                    } else {
                        *(ushort2*)(Hout + o) = make_ushort2(*(unsigned short*)&hx, *(unsigned short*)&hy);
                    }
                }
            }
        }
    }
}

// ---------------- fused GATv2 attention + aggregate + residual + LN + GELU + converts ----------------
__global__ __launch_bounds__(256) void k_aggregate(
    const float* __restrict__ att, const float* __restrict__ gbias,
    const float* __restrict__ lnw, const float* __restrict__ lnb, int layer)
{
    const int v = blockIdx.x;
    const int tid = threadIdx.x;
    const int w = tid >> 5, lane = tid & 31;
    const int c0 = w * DD + lane;

    const float* attL = att + (size_t)layer * CC;
    float a0 = attL[c0], a1 = attL[c0 + 32], a2 = attL[c0 + 64];
    const __half* xrv = g_xrh + (size_t)v * CC;
    float r0 = __half2float(xrv[c0]);
    float r1 = __half2float(xrv[c0 + 32]);
    float r2 = __half2float(xrv[c0 + 64]);

    int e0 = g_off[v], e1 = g_off[v + 1];
    float m = -INFINITY, s = 0.f, acc0 = 0.f, acc1 = 0.f, acc2 = 0.f;

    for (int e = e0; e < e1; ++e) {
        int src = g_csrsrc[e];
        const __half* xv = g_xlh + (size_t)src * CC + c0;
        float v0 = __half2float(xv[0]);
        float v1 = __half2float(xv[32]);
        float v2 = __half2float(xv[64]);
        float t0 = v0 + r0; t0 = (t0 > 0.f) ? t0 : 0.2f * t0;
        float t1 = v1 + r1; t1 = (t1 > 0.f) ? t1 : 0.2f * t1;
        float t2 = v2 + r2; t2 = (t2 > 0.f) ? t2 : 0.2f * t2;
        float p = t0 * a0 + t1 * a1 + t2 * a2;
#pragma unroll
        for (int o = 16; o > 0; o >>= 1) p += __shfl_xor_sync(0xffffffffu, p, o);
        float mn = fmaxf(m, p);
        float corr = __expf(m - mn);
        float wt = __expf(p - mn);
        s = s * corr + wt;
        acc0 = acc0 * corr + wt * v0;
        acc1 = acc1 * corr + wt * v1;
        acc2 = acc2 * corr + wt * v2;
        m = mn;
    }

    float inv = 1.f / s;
    const float* gb = gbias + (size_t)layer * CC;
    const float* hv = g_h + (size_t)v * CC;
    float t0 = acc0 * inv + gb[c0]      + hv[c0];
    float t1 = acc1 * inv + gb[c0 + 32] + hv[c0 + 32];
    float t2 = acc2 * inv + gb[c0 + 64] + hv[c0 + 64];

    float ls = t0 + t1 + t2;
    float lq = t0 * t0 + t1 * t1 + t2 * t2;
#pragma unroll
    for (int o = 16; o > 0; o >>= 1) {
        ls += __shfl_xor_sync(0xffffffffu, ls, o);
        lq += __shfl_xor_sync(0xffffffffu, lq, o);
    }
    __shared__ float shs[8], shq[8];
    if (lane == 0) { shs[w] = ls; shq[w] = lq; }
    __syncthreads();
    float S = 0.f, Q = 0.f;
#pragma unroll
    for (int i = 0; i < 8; ++i) { S += shs[i]; Q += shq[i]; }
    float mu = S * (1.f / 768.f);
    float var = Q * (1.f / 768.f) - mu * mu;
    float rs = rsqrtf(var + 1e-5f);

    const float* lw = lnw + (size_t)layer * CC;
    const float* lb = lnb + (size_t)layer * CC;
    float y0 = (t0 - mu) * rs * lw[c0]      + lb[c0];
    float y1 = (t1 - mu) * rs * lw[c0 + 32] + lb[c0 + 32];
    float y2 = (t2 - mu) * rs * lw[c0 + 64] + lb[c0 + 64];

    float gA = 0.5f * y0 * (1.f + erff(y0 * 0.70710678118654752f));
    float gB = 0.5f * y1 * (1.f + erff(y1 * 0.70710678118654752f));
    float gC = 0.5f * y2 * (1.f + erff(y2 * 0.70710678118654752f));

    float* hw = g_h + (size_t)v * CC;
    hw[c0] = gA; hw[c0 + 32] = gB; hw[c0 + 64] = gC;

    __half hA = __float2half(gA), hB = __float2half(gB), hC = __float2half(gC);

    size_t ob = (size_t)v * CC;
    g_bh[ob + c0]      = hA;
    g_bh[ob + c0 + 32] = hB;
    g_bh[ob + c0 + 64] = hC;

    __half* jw = g_jh + (size_t)v * C3 + (size_t)layer * CC;
    jw[c0]      = hA;
    jw[c0 + 32] = hB;
    jw[c0 + 64] = hC;
}

// ---------------- fused mean pool over graphs (reads fp16 JK buffer) ----------------
__global__ __launch_bounds__(256) void k_pool() {
    int g = blockIdx.x;
    int part = blockIdx.y;          // 0..2 -> layer slab
    int t = threadIdx.x;
    int s0 = g_gstart[g], s1 = g_gstart[g + 1];
    float a0 = 0.f, a1 = 0.f, a2 = 0.f;
    for (int i = s0; i < s1; ++i) {
        const __half* r = g_jh + (size_t)i * C3 + (size_t)part * CC;
        a0 += __half2float(r[t]);
        a1 += __half2float(r[t + 256]);
        a2 += __half2float(r[t + 512]);
    }
    float inv = 1.f / fmaxf((float)(s1 - s0), 1.f);
    float* o = g_pooled + (size_t)g * C3 + (size_t)part * CC;
    o[t]       = a0 * inv;
    o[t + 256] = a1 * inv;
    o[t + 512] = a2 * inv;
}

// ---------------- output LN + classifier ----------------
__global__ __launch_bounds__(256) void k_final(
    const float* __restrict__ lnw, const float* __restrict__ lnb,
    const float* __restrict__ wout, const float* __restrict__ bout,
    float* __restrict__ out)
{
    __shared__ float row[C3];
    __shared__ float red_s[8], red_q[8];
    __shared__ float sh_mu, sh_rs;
    int g = blockIdx.x, t = threadIdx.x;
    int lane = t & 31, w = t >> 5;

    float s = 0.f, q = 0.f;
    for (int c = t; c < C3; c += 256) {
        float v = g_pooled[(size_t)g * C3 + c];
        row[c] = v;
        s += v;
        q += v * v;
    }
#pragma unroll
    for (int o = 16; o > 0; o >>= 1) {
        s += __shfl_xor_sync(0xffffffffu, s, o);
        q += __shfl_xor_sync(0xffffffffu, q, o);
    }
    if (lane == 0) { red_s[w] = s; red_q[w] = q; }
    __syncthreads();
    if (t == 0) {
        float S = 0.f, Q = 0.f;
#pragma unroll
        for (int i = 0; i < 8; ++i) { S += red_s[i]; Q += red_q[i]; }
        float mu = S * (1.f / (float)C3);
        float var = Q * (1.f / (float)C3) - mu * mu;
        sh_mu = mu;
        sh_rs = rsqrtf(var + 1e-5f);
    }
    __syncthreads();
    float mu = sh_mu, rs = sh_rs;
    for (int c = t; c < C3; c += 256)
        row[c] = (row[c] - mu) * rs * lnw[c] + lnb[c];
    __syncthreads();

    for (int cls = w; cls < NCLS; cls += 8) {
        float p = 0.f;
        for (int i = lane; i < C3; i += 32)
            p += row[i] * wout[(size_t)i * NCLS + cls];
#pragma unroll
        for (int o = 16; o > 0; o >>= 1) p += __shfl_xor_sync(0xffffffffu, p, o);
        if (lane == 0) out[(size_t)g * NCLS + cls] = p + bout[cls];
    }
}

// ---------------- launch ----------------
extern "C" void kernel_launch(void* const* d_in, const int* in_sizes, int n_in,
                              void* d_out, int out_size)
{
    const float* x        = (const float*)d_in[0];
    const void*  eraw     = d_in[1];
    const void*  braw     = d_in[2];
    const float* w_in     = (const float*)d_in[3];
    const float* b_in     = (const float*)d_in[4];
    const float* Wl       = (const float*)d_in[5];
    const float* bl       = (const float*)d_in[6];
    const float* Wr       = (const float*)d_in[7];
    const float* br       = (const float*)d_in[8];
    const float* att      = (const float*)d_in[9];
    const float* gat_bias = (const float*)d_in[10];
    const float* ln_w     = (const float*)d_in[11];
    const float* ln_b     = (const float*)d_in[12];
    const float* out_ln_w = (const float*)d_in[13];
    const float* out_ln_b = (const float*)d_in[14];
    const float* w_out    = (const float*)d_in[15];
    const float* b_out    = (const float*)d_in[16];
    float* out = (float*)d_out;

    float *ph;
    __half *pah, *pbh, *pxlh, *pxrh, *pw;
    cudaGetSymbolAddress((void**)&ph,   g_h);
    cudaGetSymbolAddress((void**)&pah,  g_ah);
    cudaGetSymbolAddress((void**)&pbh,  g_bh);
    cudaGetSymbolAddress((void**)&pxlh, g_xlh);
    cudaGetSymbolAddress((void**)&pxrh, g_xrh);
    cudaGetSymbolAddress((void**)&pw,   g_wT);

    static int smem_set = 0;
    if (!smem_set) {
        cudaFuncSetAttribute(k_gemm_mma, cudaFuncAttributeMaxDynamicSharedMemorySize, GEMM_SMEM);
        smem_set = 1;
    }

    const int splitg = (NN * CC / 4 + 255) / 256;
    dim3 ggrid1(6, (NN + 127) / 128);    // input gemm: 768 cols / 128
    dim3 ggrid2(12, (NN + 127) / 128);   // fused Wl|Wr gemm: 1536 cols / 128

    // fork point: side stream starts immediately (CSR is input-independent of GEMMs)
    cudaEventRecord(g_sh.evF, 0);
    cudaStreamWaitEvent(g_sh.sB, g_sh.evF, 0);

    // ---- stream 0: compute chain (layer-0 gemm hoisted before CSR enqueue) ----
    k_transpose<<<dim3(24, 24, 7), dim3(32, 32)>>>(w_in, Wl, Wr);
    k_split_x<<<splitg, 256>>>(x);
    k_gemm_mma<<<ggrid1, 256, GEMM_SMEM>>>(pah, pw, b_in, b_in, ph, pbh, pbh, NN, 1);
    {
        const __half* BW = pw + (size_t)1 * CC * CC;
        k_gemm_mma<<<ggrid2, 256, GEMM_SMEM>>>(pbh, BW, bl, br, nullptr, pxlh, pxrh, NN, 2);
    }

    // ---- side stream: CSR build (overlaps the GEMMs above) ----
    k_detect<<<1, 1, 0, g_sh.sB>>>(eraw);
    k_prep<<<(NN + 255) / 256, 256, 0, g_sh.sB>>>();
    k_convert_count<<<(EE + 255) / 256, 256, 0, g_sh.sB>>>(eraw, braw);
    k_chsum<<<SCAN_NCH, 1024, 0, g_sh.sB>>>();
    k_choff<<<1, 32, 0, g_sh.sB>>>();
    k_offsets<<<SCAN_NCH, 1024, 0, g_sh.sB>>>();
    k_csrfill<<<(EE + 255) / 256, 256, 0, g_sh.sB>>>();
    k_gstart<<<(NN + 256) / 256, 256, 0, g_sh.sB>>>();
    cudaEventRecord(g_sh.evJ, g_sh.sB);

    // join before first aggregate (needs CSR)
    cudaStreamWaitEvent(0, g_sh.evJ, 0);

    k_aggregate<<<NN, 256>>>(att, gat_bias, ln_w, ln_b, 0);

    for (int l = 1; l < 3; ++l) {
        const __half* BW = pw + (size_t)(1 + 2 * l) * CC * CC;
        k_gemm_mma<<<ggrid2, 256, GEMM_SMEM>>>(pbh, BW,
                                               bl + (size_t)l * CC, br + (size_t)l * CC,
                                               nullptr, pxlh, pxrh, NN, 2);
        k_aggregate<<<NN, 256>>>(att, gat_bias, ln_w, ln_b, l);
    }

    k_pool<<<dim3(GG, 3), 256>>>();
    k_final<<<GG, 256>>>(out_ln_w, out_ln_b, w_out, b_out, out);

    (void)in_sizes; (void)n_in; (void)out_size;
}